// round 13
// baseline (speedup 1.0000x reference)
#include <cuda_runtime.h>
#include <math.h>

// ---------------- problem constants ----------------
#define NB    4
#define S_LEN 2048
#define DIM   512
#define NH    8
#define HD    64
#define TOK   (NB * S_LEN)          // 8192

typedef unsigned long long ull;

// ---- packed f32x2 helpers (FFMA2 path: only reachable via PTX) ----
__device__ __forceinline__ ull pk2(float a, float b)
{
    ull r; asm("mov.b64 %0, {%1, %2};" : "=l"(r) : "f"(a), "f"(b)); return r;
}
__device__ __forceinline__ ull pkdup(float a) { return pk2(a, a); }
__device__ __forceinline__ float2 unpk(ull v)
{
    float2 r; asm("mov.b64 {%0, %1}, %2;" : "=f"(r.x), "=f"(r.y) : "l"(v)); return r;
}
__device__ __forceinline__ void fma2(ull& d, ull a, ull b)
{
    asm("fma.rn.f32x2 %0, %1, %2, %0;" : "+l"(d) : "l"(a), "l"(b));
}
__device__ __forceinline__ void mul2(ull& d, ull a)
{
    asm("mul.rn.f32x2 %0, %0, %1;" : "+l"(d) : "l"(a));
}

// ---------------- scratch (no allocations allowed) ----------------
__device__ float g_h[TOK * DIM];
__device__ float g_qkv[TOK * 3 * DIM];
__device__ float g_qt[NB * NH * HD * S_LEN];   // Q^T per (b,h): [d][s], rope applied
__device__ float g_kt[NB * NH * HD * S_LEN];   // K^T per (b,h): [d][s], rope applied
__device__ float g_att[TOK * DIM];
__device__ float g_x1[TOK * DIM];
__device__ float g_mid[TOK * 4 * DIM];

// ---------------- LayerNorm ----------------
__global__ void __launch_bounds__(256) ln_kernel(const float* __restrict__ x,
                                                 const float* __restrict__ g,
                                                 const float* __restrict__ b,
                                                 float* __restrict__ out)
{
    int row = blockIdx.x;
    int t = threadIdx.x;
    const float2* xr = (const float2*)(x + (size_t)row * DIM);
    float2 v = xr[t];
    float s = v.x + v.y;
    float ss = v.x * v.x + v.y * v.y;
#pragma unroll
    for (int m = 16; m; m >>= 1) {
        s  += __shfl_xor_sync(0xffffffffu, s, m);
        ss += __shfl_xor_sync(0xffffffffu, ss, m);
    }
    __shared__ float sh[16];
    int w = t >> 5;
    if ((t & 31) == 0) { sh[w] = s; sh[8 + w] = ss; }
    __syncthreads();
    s = 0.f; ss = 0.f;
#pragma unroll
    for (int i = 0; i < 8; i++) { s += sh[i]; ss += sh[8 + i]; }
    float mu  = s * (1.f / DIM);
    float var = ss * (1.f / DIM) - mu * mu;
    float inv = rsqrtf(var + 1e-5f);
    float2 gg = ((const float2*)g)[t];
    float2 bb = ((const float2*)b)[t];
    float2 o;
    o.x = (v.x - mu) * inv * gg.x + bb.x;
    o.y = (v.y - mu) * inv * gg.y + bb.y;
    ((float2*)(out + (size_t)row * DIM))[t] = o;
}

// ---------------- fused RoPE + transpose of Q,K into [bh][d][s] ----------------
__global__ void __launch_bounds__(256) qk_rope_transpose(const float* __restrict__ qkv,
                                                         const float* __restrict__ cb,
                                                         const float* __restrict__ sb,
                                                         float* __restrict__ qt,
                                                         float* __restrict__ kt)
{
    __shared__ float tq[32][65], tk[32][65], tc[32][65], tss[32][65];
    int s0 = blockIdx.x * 32;
    int bh = blockIdx.y;
    int b = bh >> 3, h = bh & 7;
    int tid = threadIdx.x;
    int d = tid & 63, sl = tid >> 6;
#pragma unroll
    for (int it = 0; it < 8; it++) {
        int s = sl + it * 4;
        size_t ro = ((size_t)(b * S_LEN + s0 + s)) * (3 * DIM) + h * HD + d;
        tq[s][d]  = qkv[ro];
        tk[s][d]  = qkv[ro + DIM];
        tc[s][d]  = cb[(s0 + s) * HD + d];
        tss[s][d] = sb[(s0 + s) * HD + d];
    }
    __syncthreads();
    int sw = tid & 31, dw = tid >> 5;
#pragma unroll
    for (int it = 0; it < 8; it++) {
        int dd = dw + it * 8;
        float c = tc[sw][dd], sn = tss[sw][dd];
        float q0 = tq[sw][dd], q1 = tq[sw][dd ^ 32];
        float k0 = tk[sw][dd], k1 = tk[sw][dd ^ 32];
        float rq = (dd < 32) ? (q0 * c - q1 * sn) : (q0 * c + q1 * sn);
        float rk = (dd < 32) ? (k0 * c - k1 * sn) : (k0 * c + k1 * sn);
        size_t wo = ((size_t)bh * HD + dd) * S_LEN + s0 + sw;
        qt[wo] = rq;
        kt[wo] = rk;
    }
}

// ---------------- 128x128x16 GEMM, 256 threads, 8x8/thread, FFMA2, dbuf ----------------
__device__ __forceinline__ float gelu_f(float x)
{
    return 0.5f * x * (1.f + erff(x * 0.7071067811865476f));
}

template <int EPI>
__global__ void __launch_bounds__(256) gemm_kernel(const float* __restrict__ A,
                                                   const float* __restrict__ B,
                                                   const float* __restrict__ bias,
                                                   const float* __restrict__ R,
                                                   float* __restrict__ C,
                                                   int M, int N, int K)
{
    __shared__ __align__(16) float As[2][16][132];   // transposed: As[k][m]
    __shared__ __align__(16) float Bs[2][16][128];

    int tid = threadIdx.x;
    int lane = tid & 31, w = tid >> 5;             // w: 0..7
    int tx = (lane & 3) | ((w & 3) << 2);          // 0..15 col-group
    int ty = (lane >> 2) | ((w >> 2) << 3);        // 0..15 row-group
    int m0 = blockIdx.y * 128, n0 = blockIdx.x * 128;

    // load indices
    int ar = (tid << 0) >> 2;                       // for A: r = i>>2 (per-iter offset)
    (void)ar;

    ull acc2[8][4];
#pragma unroll
    for (int i = 0; i < 8; i++)
#pragma unroll
        for (int j = 0; j < 4; j++) acc2[i][j] = 0ull;

    int nT = K >> 4;

    // prologue: tile 0 -> buffer 0
#pragma unroll
    for (int it = 0; it < 2; ++it) {
        int i = tid + it * 256;
        int r = i >> 2, c = i & 3;
        float4 v = *(const float4*)&A[(size_t)(m0 + r) * K + c * 4];
        As[0][c * 4 + 0][r] = v.x; As[0][c * 4 + 1][r] = v.y;
        As[0][c * 4 + 2][r] = v.z; As[0][c * 4 + 3][r] = v.w;
    }
#pragma unroll
    for (int it = 0; it < 2; ++it) {
        int i = tid + it * 256;
        int r = i >> 5, c = i & 31;
        *(float4*)&Bs[0][r][c * 4] = *(const float4*)&B[(size_t)r * N + n0 + c * 4];
    }
    __syncthreads();

    int cur = 0;
    for (int t = 0; t < nT; ++t) {
        float4 va[2], vb[2];
        bool more = (t + 1 < nT);
        if (more) {
#pragma unroll
            for (int it = 0; it < 2; ++it) {
                int i = tid + it * 256;
                int r = i >> 2, c = i & 3;
                va[it] = *(const float4*)&A[(size_t)(m0 + r) * K + (t + 1) * 16 + c * 4];
            }
#pragma unroll
            for (int it = 0; it < 2; ++it) {
                int i = tid + it * 256;
                int r = i >> 5, c = i & 31;
                vb[it] = *(const float4*)&B[(size_t)((t + 1) * 16 + r) * N + n0 + c * 4];
            }
        }
        // compute on buffer cur
#pragma unroll
        for (int k = 0; k < 16; k++) {
            float4 a0 = *(const float4*)&As[cur][k][ty * 8];
            float4 a1 = *(const float4*)&As[cur][k][ty * 8 + 4];
            ulonglong2 b0 = *(const ulonglong2*)&Bs[cur][k][tx * 8];
            ulonglong2 b1 = *(const ulonglong2*)&Bs[cur][k][tx * 8 + 4];
            ull bv[4] = {b0.x, b0.y, b1.x, b1.y};
            ull ad[8] = {pkdup(a0.x), pkdup(a0.y), pkdup(a0.z), pkdup(a0.w),
                         pkdup(a1.x), pkdup(a1.y), pkdup(a1.z), pkdup(a1.w)};
#pragma unroll
            for (int i = 0; i < 8; i++)
#pragma unroll
                for (int j = 0; j < 4; j++) fma2(acc2[i][j], ad[i], bv[j]);
        }
        if (more) {
            int nxt = cur ^ 1;
#pragma unroll
            for (int it = 0; it < 2; ++it) {
                int i = tid + it * 256;
                int r = i >> 2, c = i & 3;
                As[nxt][c * 4 + 0][r] = va[it].x; As[nxt][c * 4 + 1][r] = va[it].y;
                As[nxt][c * 4 + 2][r] = va[it].z; As[nxt][c * 4 + 3][r] = va[it].w;
            }
#pragma unroll
            for (int it = 0; it < 2; ++it) {
                int i = tid + it * 256;
                int r = i >> 5, c = i & 31;
                *(float4*)&Bs[nxt][r][c * 4] = vb[it];
            }
        }
        __syncthreads();
        cur ^= 1;
    }

    // epilogue
    float4 bias0 = *(const float4*)&bias[n0 + tx * 8];
    float4 bias1 = *(const float4*)&bias[n0 + tx * 8 + 4];
    float bb[8] = {bias0.x, bias0.y, bias0.z, bias0.w, bias1.x, bias1.y, bias1.z, bias1.w};
#pragma unroll
    for (int i = 0; i < 8; i++) {
        int m = m0 + ty * 8 + i;
        size_t off = (size_t)m * N + n0 + tx * 8;
        float2 u0 = unpk(acc2[i][0]), u1 = unpk(acc2[i][1]);
        float2 u2 = unpk(acc2[i][2]), u3 = unpk(acc2[i][3]);
        float vv[8] = {u0.x, u0.y, u1.x, u1.y, u2.x, u2.y, u3.x, u3.y};
#pragma unroll
        for (int j = 0; j < 8; j++) {
            float v = vv[j] + bb[j];
            if (EPI == 1) v = gelu_f(v);
            vv[j] = v;
        }
        if (EPI == 2) {
            float4 r0 = *(const float4*)&R[off];
            float4 r1 = *(const float4*)&R[off + 4];
            vv[0] += r0.x; vv[1] += r0.y; vv[2] += r0.z; vv[3] += r0.w;
            vv[4] += r1.x; vv[5] += r1.y; vv[6] += r1.z; vv[7] += r1.w;
        }
        *(float4*)&C[off]     = make_float4(vv[0], vv[1], vv[2], vv[3]);
        *(float4*)&C[off + 4] = make_float4(vv[4], vv[5], vv[6], vv[7]);
    }
}

// ---------------- flash attention: 256 q-rows/CTA, 256 threads, 8x8/thread ----------------
// grid (S/256, NH, NB). smem: Qt[64][260] | Kt[64][68] | Vs[64][68] | Ps[256][68]
#define AQ 260
#define AK 68
#define ATT_SMEM_FLOATS (64 * AQ + 64 * AK + 64 * AK + 256 * AK)

__global__ void __launch_bounds__(256) attn_kernel(const float* __restrict__ qtg,
                                                   const float* __restrict__ ktg,
                                                   const float* __restrict__ qkv,
                                                   float* __restrict__ out)
{
    extern __shared__ __align__(16) float smem[];
    float (*Qt)[AQ] = (float(*)[AQ])(smem);
    float (*Kt)[AK] = (float(*)[AK])(smem + 64 * AQ);
    float (*Vs)[AK] = (float(*)[AK])(smem + 64 * AQ + 64 * AK);
    float (*Ps)[AK] = (float(*)[AK])(smem + 64 * AQ + 2 * 64 * AK);

    int tid = threadIdx.x;
    int lane = tid & 31, w = tid >> 5;             // w: 0..7
    int tx = (lane & 3) | ((lane >> 2) & 4);       // 0..7 key-col group (lane bits {0,1,4})
    int ty = ((lane >> 2) & 3) | (w << 2);         // 0..31 q-row group (8 rows each)
    int qt = blockIdx.x, h = blockIdx.y, b = blockIdx.z;
    int bh = b * NH + h;

    const float* Qg = qtg + (size_t)bh * HD * S_LEN + qt * 256;
    const float* Kg = ktg + (size_t)bh * HD * S_LEN;
    const float* Vg = qkv + (size_t)b * S_LEN * (3 * DIM) + 2 * DIM + h * HD;

    // load Q^T tile: 64 d-rows x 256 s-cols (4096 float4 / 256 thr = 16 iters)
#pragma unroll
    for (int it = 0; it < 16; ++it) {
        int i = tid + it * 256;
        int d = i >> 6, c = i & 63;
        *(float4*)&Qt[d][c * 4] = *(const float4*)&Qg[(size_t)d * S_LEN + c * 4];
    }

    float m_r[8], l_r[8];
    ull accO2[8][4];
#pragma unroll
    for (int i = 0; i < 8; i++) {
        m_r[i] = -1e30f; l_r[i] = 0.f;
#pragma unroll
        for (int j = 0; j < 4; j++) accO2[i][j] = 0ull;
    }
    const float scale = 0.125f;   // 1/sqrt(64)

    for (int nt = 0; nt < S_LEN / 64; ++nt) {
        __syncthreads();
        // K^T tile (64 d x 64 s) + V tile (64 tok x 64 d): 1024 f4 each / 256 thr
#pragma unroll
        for (int it = 0; it < 4; ++it) {
            int i = tid + it * 256;
            int r = i >> 4, c = i & 15;
            *(float4*)&Kt[r][c * 4] =
                *(const float4*)&Kg[(size_t)r * S_LEN + nt * 64 + c * 4];
            *(float4*)&Vs[r][c * 4] =
                *(const float4*)&Vg[(size_t)(nt * 64 + r) * (3 * DIM) + c * 4];
        }
        __syncthreads();

        // S = Q^T(K^T): 8 q-rows x 8 keys per thread, packed over key pairs
        ull s2[8][4];
#pragma unroll
        for (int i = 0; i < 8; i++)
#pragma unroll
            for (int j = 0; j < 4; j++) s2[i][j] = 0ull;
#pragma unroll 4
        for (int d = 0; d < 64; ++d) {
            float4 a0 = *(const float4*)&Qt[d][ty * 8];
            float4 a1 = *(const float4*)&Qt[d][ty * 8 + 4];
            ulonglong2 b0 = *(const ulonglong2*)&Kt[d][tx * 8];
            ulonglong2 b1 = *(const ulonglong2*)&Kt[d][tx * 8 + 4];
            ull bv[4] = {b0.x, b0.y, b1.x, b1.y};
            ull ad[8] = {pkdup(a0.x), pkdup(a0.y), pkdup(a0.z), pkdup(a0.w),
                         pkdup(a1.x), pkdup(a1.y), pkdup(a1.z), pkdup(a1.w)};
#pragma unroll
            for (int i = 0; i < 8; i++)
#pragma unroll
                for (int j = 0; j < 4; j++) fma2(s2[i][j], ad[i], bv[j]);
        }

        // online softmax (row spans tx lanes -> shuffle masks 1,2,16)
#pragma unroll
        for (int i = 0; i < 8; i++) {
            float2 t0 = unpk(s2[i][0]), t1 = unpk(s2[i][1]);
            float2 t2 = unpk(s2[i][2]), t3 = unpk(s2[i][3]);
            float sv[8] = {t0.x, t0.y, t1.x, t1.y, t2.x, t2.y, t3.x, t3.y};
            float mt = -1e30f;
#pragma unroll
            for (int j = 0; j < 8; j++) { sv[j] *= scale; mt = fmaxf(mt, sv[j]); }
            mt = fmaxf(mt, __shfl_xor_sync(0xffffffffu, mt, 1));
            mt = fmaxf(mt, __shfl_xor_sync(0xffffffffu, mt, 2));
            mt = fmaxf(mt, __shfl_xor_sync(0xffffffffu, mt, 16));
            float mn = fmaxf(m_r[i], mt);
            float alpha = __expf(m_r[i] - mn);
            float rs = 0.f;
            float p[8];
#pragma unroll
            for (int j = 0; j < 8; j++) { p[j] = __expf(sv[j] - mn); rs += p[j]; }
            *(float4*)&Ps[ty * 8 + i][tx * 8]     = make_float4(p[0], p[1], p[2], p[3]);
            *(float4*)&Ps[ty * 8 + i][tx * 8 + 4] = make_float4(p[4], p[5], p[6], p[7]);
            rs += __shfl_xor_sync(0xffffffffu, rs, 1);
            rs += __shfl_xor_sync(0xffffffffu, rs, 2);
            rs += __shfl_xor_sync(0xffffffffu, rs, 16);
            l_r[i] = l_r[i] * alpha + rs;
            m_r[i] = mn;
            ull al2 = pkdup(alpha);
#pragma unroll
            for (int j = 0; j < 4; j++) mul2(accO2[i][j], al2);
        }
        __syncthreads();   // Ps visible

        // O += P @ V
#pragma unroll 4
        for (int j = 0; j < 64; ++j) {
            ulonglong2 v0 = *(const ulonglong2*)&Vs[j][tx * 8];
            ulonglong2 v1 = *(const ulonglong2*)&Vs[j][tx * 8 + 4];
            ull vb[4] = {v0.x, v0.y, v1.x, v1.y};
#pragma unroll
            for (int i = 0; i < 8; i++) {
                ull pd = pkdup(Ps[ty * 8 + i][j]);
#pragma unroll
                for (int c = 0; c < 4; c++) fma2(accO2[i][c], pd, vb[c]);
            }
        }
    }

    // write O (b, s, h*HD + d)
#pragma unroll
    for (int i = 0; i < 8; i++) {
        float inv = 1.f / l_r[i];
        int row = b * S_LEN + qt * 256 + ty * 8 + i;
        size_t off = (size_t)row * DIM + h * HD + tx * 8;
        float2 u0 = unpk(accO2[i][0]), u1 = unpk(accO2[i][1]);
        float2 u2 = unpk(accO2[i][2]), u3 = unpk(accO2[i][3]);
        *(float4*)&out[off]     = make_float4(u0.x * inv, u0.y * inv, u1.x * inv, u1.y * inv);
        *(float4*)&out[off + 4] = make_float4(u2.x * inv, u2.y * inv, u3.x * inv, u3.y * inv);
    }
}

// ---------------- launcher ----------------
extern "C" void kernel_launch(void* const* d_in, const int* in_sizes, int n_in,
                              void* d_out, int out_size)
{
    const float* x        = (const float*)d_in[0];
    const float* rope_cos = (const float*)d_in[1];
    const float* rope_sin = (const float*)d_in[2];
    const float* n1g      = (const float*)d_in[3];
    const float* n1b      = (const float*)d_in[4];
    const float* n2g      = (const float*)d_in[5];
    const float* n2b      = (const float*)d_in[6];
    const float* w_qkv    = (const float*)d_in[7];
    const float* b_qkv    = (const float*)d_in[8];
    const float* w_proj   = (const float*)d_in[9];
    const float* b_proj   = (const float*)d_in[10];
    const float* w_fc1    = (const float*)d_in[11];
    const float* b_fc1    = (const float*)d_in[12];
    const float* w_fc2    = (const float*)d_in[13];
    const float* b_fc2    = (const float*)d_in[14];
    float* out = (float*)d_out;

    float *ph, *pqkv, *pqt, *pkt, *patt, *px1, *pmid;
    cudaGetSymbolAddress((void**)&ph,   g_h);
    cudaGetSymbolAddress((void**)&pqkv, g_qkv);
    cudaGetSymbolAddress((void**)&pqt,  g_qt);
    cudaGetSymbolAddress((void**)&pkt,  g_kt);
    cudaGetSymbolAddress((void**)&patt, g_att);
    cudaGetSymbolAddress((void**)&px1,  g_x1);
    cudaGetSymbolAddress((void**)&pmid, g_mid);

    cudaFuncSetAttribute(attn_kernel, cudaFuncAttributeMaxDynamicSharedMemorySize,
                         ATT_SMEM_FLOATS * (int)sizeof(float));

    // 1) LN1
    ln_kernel<<<TOK, 256>>>(x, n1g, n1b, ph);
    // 2) QKV GEMM + bias
    gemm_kernel<0><<<dim3(3 * DIM / 128, TOK / 128), 256>>>(ph, w_qkv, b_qkv, nullptr, pqkv,
                                                            TOK, 3 * DIM, DIM);
    // 3) fused RoPE + transpose of Q,K -> [bh][d][s]
    qk_rope_transpose<<<dim3(S_LEN / 32, NB * NH), 256>>>(pqkv, rope_cos, rope_sin,
                                                          pqt, pkt);
    // 4) attention
    attn_kernel<<<dim3(S_LEN / 256, NH, NB), 256, ATT_SMEM_FLOATS * sizeof(float)>>>(
        pqt, pkt, pqkv, patt);
    // 5) proj + bias + residual(x)
    gemm_kernel<2><<<dim3(DIM / 128, TOK / 128), 256>>>(patt, w_proj, b_proj, x, px1,
                                                        TOK, DIM, DIM);
    // 6) LN2
    ln_kernel<<<TOK, 256>>>(px1, n2g, n2b, ph);
    // 7) FC1 + bias + GELU
    gemm_kernel<1><<<dim3(4 * DIM / 128, TOK / 128), 256>>>(ph, w_fc1, b_fc1, nullptr, pmid,
                                                            TOK, 4 * DIM, DIM);
    // 8) FC2 + bias + residual(x1) -> out
    gemm_kernel<2><<<dim3(DIM / 128, TOK / 128), 256>>>(pmid, w_fc2, b_fc2, px1, out,
                                                        TOK, DIM, 4 * DIM);
}

// round 15
// speedup vs baseline: 1.4258x; 1.4258x over previous
#include <cuda_runtime.h>
#include <cuda_bf16.h>
#include <math.h>
#include <stdint.h>

// ---------------- problem constants ----------------
#define NB    4
#define S_LEN 2048
#define DIM   512
#define NH    8
#define HD    64
#define TOK   (NB * S_LEN)          // 8192

typedef unsigned long long ull;

// ---- packed f32x2 helpers (FFMA2, attention) ----
__device__ __forceinline__ ull pk2(float a, float b)
{
    ull r; asm("mov.b64 %0, {%1, %2};" : "=l"(r) : "f"(a), "f"(b)); return r;
}
__device__ __forceinline__ ull pkdup(float a) { return pk2(a, a); }
__device__ __forceinline__ float2 unpk(ull v)
{
    float2 r; asm("mov.b64 {%0, %1}, %2;" : "=f"(r.x), "=f"(r.y) : "l"(v)); return r;
}
__device__ __forceinline__ void fma2(ull& d, ull a, ull b)
{
    asm("fma.rn.f32x2 %0, %1, %2, %0;" : "+l"(d) : "l"(a), "l"(b));
}
__device__ __forceinline__ void mul2(ull& d, ull a)
{
    asm("mul.rn.f32x2 %0, %0, %1;" : "+l"(d) : "l"(a));
}

// ---- mma.sync helpers (baseline PTX, compiles under compute_103) ----
__device__ __forceinline__ uint32_t smem_u32(const void* p)
{
    uint32_t a;
    asm("{ .reg .u64 t; cvta.to.shared.u64 t, %1; cvt.u32.u64 %0, t; }"
        : "=r"(a) : "l"(p));
    return a;
}
__device__ __forceinline__ void ldsm_x4(uint32_t* r, uint32_t addr)
{
    asm volatile("ldmatrix.sync.aligned.m8n8.x4.shared.b16 {%0,%1,%2,%3}, [%4];"
                 : "=r"(r[0]), "=r"(r[1]), "=r"(r[2]), "=r"(r[3]) : "r"(addr));
}
__device__ __forceinline__ void mma16816(float* d, const uint32_t* a, const uint32_t* b)
{
    asm volatile("mma.sync.aligned.m16n8k16.row.col.f32.bf16.bf16.f32 "
                 "{%0,%1,%2,%3}, {%4,%5,%6,%7}, {%8,%9}, {%0,%1,%2,%3};"
                 : "+f"(d[0]), "+f"(d[1]), "+f"(d[2]), "+f"(d[3])
                 : "r"(a[0]), "r"(a[1]), "r"(a[2]), "r"(a[3]), "r"(b[0]), "r"(b[1]));
}

// ---------------- scratch (no allocations allowed) ----------------
__device__ __nv_bfloat16 g_hh[TOK * DIM],  g_hl[TOK * DIM];     // LN out hi/lo
__device__ float g_qkv[TOK * 3 * DIM];
__device__ float g_qt[NB * NH * HD * S_LEN];
__device__ float g_kt[NB * NH * HD * S_LEN];
__device__ __nv_bfloat16 g_atth[TOK * DIM], g_attl[TOK * DIM];  // attention out hi/lo
__device__ float g_x1[TOK * DIM];
__device__ __nv_bfloat16 g_midh[TOK * 4 * DIM], g_midl[TOK * 4 * DIM];
// weight scratch: transposed [N][K] bf16 hi/lo
__device__ __nv_bfloat16 g_wqkvh[3 * DIM * DIM], g_wqkvl[3 * DIM * DIM];
__device__ __nv_bfloat16 g_wprojh[DIM * DIM],    g_wprojl[DIM * DIM];
__device__ __nv_bfloat16 g_wfc1h[4 * DIM * DIM], g_wfc1l[4 * DIM * DIM];
__device__ __nv_bfloat16 g_wfc2h[4 * DIM * DIM], g_wfc2l[4 * DIM * DIM];

__device__ __forceinline__ void split_bf16(float v, __nv_bfloat16& hi, __nv_bfloat16& lo)
{
    hi = __float2bfloat16(v);
    lo = __float2bfloat16(v - __bfloat162float(hi));
}

// ---------------- weight transpose + split: W[K][N] fp32 -> out[N][K] bf16 hi/lo ----------------
__global__ void __launch_bounds__(256) wsplit(const float* __restrict__ W,
                                              __nv_bfloat16* __restrict__ th,
                                              __nv_bfloat16* __restrict__ tl,
                                              int K, int N)
{
    __shared__ float t[32][33];
    int n0 = blockIdx.x * 32, k0 = blockIdx.y * 32;
    int j = threadIdx.x & 31, i0 = threadIdx.x >> 5;
#pragma unroll
    for (int it = 0; it < 4; it++) {
        int i = i0 + it * 8;
        t[i][j] = W[(size_t)(k0 + i) * N + n0 + j];
    }
    __syncthreads();
#pragma unroll
    for (int it = 0; it < 4; it++) {
        int i = i0 + it * 8;
        float v = t[j][i];
        __nv_bfloat16 hv, lv; split_bf16(v, hv, lv);
        size_t o = (size_t)(n0 + i) * K + k0 + j;
        th[o] = hv; tl[o] = lv;
    }
}

// ---------------- LayerNorm -> bf16 hi/lo ----------------
__global__ void __launch_bounds__(256) ln_kernel(const float* __restrict__ x,
                                                 const float* __restrict__ g,
                                                 const float* __restrict__ b,
                                                 __nv_bfloat16* __restrict__ oh,
                                                 __nv_bfloat16* __restrict__ ol)
{
    int row = blockIdx.x;
    int t = threadIdx.x;
    const float2* xr = (const float2*)(x + (size_t)row * DIM);
    float2 v = xr[t];
    float s = v.x + v.y;
    float ss = v.x * v.x + v.y * v.y;
#pragma unroll
    for (int m = 16; m; m >>= 1) {
        s  += __shfl_xor_sync(0xffffffffu, s, m);
        ss += __shfl_xor_sync(0xffffffffu, ss, m);
    }
    __shared__ float sh[16];
    int w = t >> 5;
    if ((t & 31) == 0) { sh[w] = s; sh[8 + w] = ss; }
    __syncthreads();
    s = 0.f; ss = 0.f;
#pragma unroll
    for (int i = 0; i < 8; i++) { s += sh[i]; ss += sh[8 + i]; }
    float mu  = s * (1.f / DIM);
    float var = ss * (1.f / DIM) - mu * mu;
    float inv = rsqrtf(var + 1e-5f);
    float2 gg = ((const float2*)g)[t];
    float2 bb = ((const float2*)b)[t];
    float vx = (v.x - mu) * inv * gg.x + bb.x;
    float vy = (v.y - mu) * inv * gg.y + bb.y;
    size_t idx = (size_t)row * DIM + 2 * t;
    __nv_bfloat16 h0, l0, h1, l1;
    split_bf16(vx, h0, l0); split_bf16(vy, h1, l1);
    oh[idx] = h0; oh[idx + 1] = h1;
    ol[idx] = l0; ol[idx + 1] = l1;
}

// ---------------- fused RoPE + transpose of Q,K into [bh][d][s] ----------------
__global__ void __launch_bounds__(256) qk_rope_transpose(const float* __restrict__ qkv,
                                                         const float* __restrict__ cb,
                                                         const float* __restrict__ sb,
                                                         float* __restrict__ qt,
                                                         float* __restrict__ kt)
{
    __shared__ float tq[32][65], tk[32][65], tc[32][65], tss[32][65];
    int s0 = blockIdx.x * 32;
    int bh = blockIdx.y;
    int b = bh >> 3, h = bh & 7;
    int tid = threadIdx.x;
    int d = tid & 63, sl = tid >> 6;
#pragma unroll
    for (int it = 0; it < 8; it++) {
        int s = sl + it * 4;
        size_t ro = ((size_t)(b * S_LEN + s0 + s)) * (3 * DIM) + h * HD + d;
        tq[s][d]  = qkv[ro];
        tk[s][d]  = qkv[ro + DIM];
        tc[s][d]  = cb[(s0 + s) * HD + d];
        tss[s][d] = sb[(s0 + s) * HD + d];
    }
    __syncthreads();
    int sw = tid & 31, dw = tid >> 5;
#pragma unroll
    for (int it = 0; it < 8; it++) {
        int dd = dw + it * 8;
        float c = tc[sw][dd], sn = tss[sw][dd];
        float q0 = tq[sw][dd], q1 = tq[sw][dd ^ 32];
        float k0 = tk[sw][dd], k1 = tk[sw][dd ^ 32];
        float rq = (dd < 32) ? (q0 * c - q1 * sn) : (q0 * c + q1 * sn);
        float rk = (dd < 32) ? (k0 * c - k1 * sn) : (k0 * c + k1 * sn);
        size_t wo = ((size_t)bh * HD + dd) * S_LEN + s0 + sw;
        qt[wo] = rq;
        kt[wo] = rk;
    }
}

// ---------------- mma.sync bf16x3 GEMM: C[M,N] = A[M,K] @ B'[N,K]^T ----------------
// A as bf16 hi/lo [M][K]; B as bf16 hi/lo [N][K] (pre-transposed weights).
// 128x128x32 CTA tile, 256 threads = 8 warps (4 m x 2 n), warp tile 32x64.
// EPI: 0 none, 1 gelu, 2 +R.  OUT: 0 fp32 C, 1 bf16 hi/lo (Ch/Cl).
__device__ __forceinline__ float gelu_f(float x)
{
    return 0.5f * x * (1.f + erff(x * 0.7071067811865476f));
}

#define GPAD 40   // smem row pitch in bf16 (80B: conflict-free ldmatrix)

template <int EPI, int OUT>
__global__ void __launch_bounds__(256) mma_gemm(const __nv_bfloat16* __restrict__ Ah,
                                                const __nv_bfloat16* __restrict__ Al,
                                                const __nv_bfloat16* __restrict__ Bh,
                                                const __nv_bfloat16* __restrict__ Bl,
                                                const float* __restrict__ bias,
                                                const float* __restrict__ R,
                                                float* __restrict__ C,
                                                __nv_bfloat16* __restrict__ Ch,
                                                __nv_bfloat16* __restrict__ Cl,
                                                int M, int N, int K)
{
    __shared__ __align__(16) __nv_bfloat16 sAh[128 * GPAD], sAl[128 * GPAD];
    __shared__ __align__(16) __nv_bfloat16 sBh[128 * GPAD], sBl[128 * GPAD];

    int tid = threadIdx.x, lane = tid & 31, wid = tid >> 5;
    int wm = wid & 3, wn = wid >> 2;               // warp tile: rows wm*32, cols wn*64
    int m0 = blockIdx.y * 128, n0 = blockIdx.x * 128;

    uint32_t uAh = smem_u32(sAh), uAl = smem_u32(sAl);
    uint32_t uBh = smem_u32(sBh), uBl = smem_u32(sBl);

    // per-lane ldmatrix addresses (byte offsets within tile)
    // A (x4, m16k16): row = mbase + (lane&15), colseg = (lane>>4)*8
    uint32_t aoff = (uint32_t)((lane & 15) * GPAD + (lane >> 4) * 8) * 2;
    // B (x4, two n-tiles): row = nbase + ((lane>>4)&1)*8 + (lane&7), colseg = ((lane>>3)&1)*8
    uint32_t boff = (uint32_t)((((lane >> 4) & 1) * 8 + (lane & 7)) * GPAD +
                               ((lane >> 3) & 1) * 8) * 2;

    float acc[2][8][4];
#pragma unroll
    for (int i = 0; i < 2; i++)
#pragma unroll
        for (int j = 0; j < 8; j++)
#pragma unroll
            for (int c = 0; c < 4; c++) acc[i][j][c] = 0.f;

    for (int kk = 0; kk < K; kk += 32) {
        // load 4 tiles: 128 rows x 32 bf16 (4 x 16B segs per row)
#pragma unroll
        for (int it = 0; it < 2; ++it) {
            int u = tid + it * 256;
            int r = u >> 2, sg = u & 3;
            size_t ga = (size_t)(m0 + r) * K + kk + sg * 8;
            size_t gb = (size_t)(n0 + r) * K + kk + sg * 8;
            int so = r * GPAD + sg * 8;
            *(uint4*)&sAh[so] = *(const uint4*)&Ah[ga];
            *(uint4*)&sAl[so] = *(const uint4*)&Al[ga];
            *(uint4*)&sBh[so] = *(const uint4*)&Bh[gb];
            *(uint4*)&sBl[so] = *(const uint4*)&Bl[gb];
        }
        __syncthreads();

#pragma unroll
        for (int k16 = 0; k16 < 2; ++k16) {
            uint32_t kb = (uint32_t)(k16 * 16 * 2);
            uint32_t ah[2][4], al[2][4];
#pragma unroll
            for (int mt = 0; mt < 2; ++mt) {
                uint32_t ro = (uint32_t)((wm * 32 + mt * 16) * GPAD * 2) + kb + aoff;
                ldsm_x4(ah[mt], uAh + ro);
                ldsm_x4(al[mt], uAl + ro);
            }
            uint32_t bh[4][4], bl[4][4];
#pragma unroll
            for (int p = 0; p < 4; ++p) {
                uint32_t ro = (uint32_t)((wn * 64 + p * 16) * GPAD * 2) + kb + boff;
                ldsm_x4(bh[p], uBh + ro);
                ldsm_x4(bl[p], uBl + ro);
            }
#pragma unroll
            for (int mt = 0; mt < 2; ++mt)
#pragma unroll
                for (int nt = 0; nt < 8; ++nt) {
                    const uint32_t* fh = &bh[nt >> 1][(nt & 1) * 2];
                    const uint32_t* fl = &bl[nt >> 1][(nt & 1) * 2];
                    mma16816(acc[mt][nt], ah[mt], fh);
                    mma16816(acc[mt][nt], ah[mt], fl);
                    mma16816(acc[mt][nt], al[mt], fh);
                }
        }
        __syncthreads();
    }

    // epilogue: lane l of atom (mt, nt) owns (row, col), (row, col+1), (row+8, col), (row+8, col+1)
#pragma unroll
    for (int mt = 0; mt < 2; ++mt) {
#pragma unroll
        for (int nt = 0; nt < 8; ++nt) {
            int row = m0 + wm * 32 + mt * 16 + (lane >> 2);
            int col = n0 + wn * 64 + nt * 8 + (lane & 3) * 2;
            float b0 = bias[col], b1 = bias[col + 1];
#pragma unroll
            for (int half = 0; half < 2; ++half) {
                int r = row + half * 8;
                float v0 = acc[mt][nt][half * 2 + 0] + b0;
                float v1 = acc[mt][nt][half * 2 + 1] + b1;
                if (EPI == 1) { v0 = gelu_f(v0); v1 = gelu_f(v1); }
                size_t off = (size_t)r * N + col;
                if (EPI == 2) {
                    float2 rr = *(const float2*)&R[off];
                    v0 += rr.x; v1 += rr.y;
                }
                if (OUT == 0) {
                    *(float2*)&C[off] = make_float2(v0, v1);
                } else {
                    __nv_bfloat16 h0, l0, h1, l1;
                    split_bf16(v0, h0, l0); split_bf16(v1, h1, l1);
                    *(__nv_bfloat162*)&Ch[off] = __nv_bfloat162(h0, h1);
                    *(__nv_bfloat162*)&Cl[off] = __nv_bfloat162(l0, l1);
                }
            }
        }
    }
}

// ---------------- flash attention (R12 config): 128 q/CTA, 256 thr, 4x8, FFMA2 ----------------
#define AQ 132
#define AK 68
#define ATT_SMEM_FLOATS (64 * AQ + 64 * AK + 64 * AK + 128 * AK)

__global__ void __launch_bounds__(256) attn_kernel(const float* __restrict__ qtg,
                                                   const float* __restrict__ ktg,
                                                   const float* __restrict__ qkv,
                                                   __nv_bfloat16* __restrict__ outh,
                                                   __nv_bfloat16* __restrict__ outl)
{
    extern __shared__ __align__(16) float smem[];
    float (*Qt)[AQ] = (float(*)[AQ])(smem);
    float (*Kt)[AK] = (float(*)[AK])(smem + 64 * AQ);
    float (*Vs)[AK] = (float(*)[AK])(smem + 64 * AQ + 64 * AK);
    float (*Ps)[AK] = (float(*)[AK])(smem + 64 * AQ + 2 * 64 * AK);

    int tid = threadIdx.x;
    int lane = tid & 31, w = tid >> 5;
    int tx = (lane & 3) | ((lane >> 2) & 4);
    int ty = ((lane >> 2) & 3) | (w << 2);
    int qt = blockIdx.x, h = blockIdx.y, b = blockIdx.z;
    int bh = b * NH + h;

    const float* Qg = qtg + (size_t)bh * HD * S_LEN + qt * 128;
    const float* Kg = ktg + (size_t)bh * HD * S_LEN;
    const float* Vg = qkv + (size_t)b * S_LEN * (3 * DIM) + 2 * DIM + h * HD;

#pragma unroll
    for (int it = 0; it < 8; ++it) {
        int i = tid + it * 256;
        int d = i >> 5, c = i & 31;
        *(float4*)&Qt[d][c * 4] = *(const float4*)&Qg[(size_t)d * S_LEN + c * 4];
    }

    float m_r[4], l_r[4];
    ull accO2[4][4];
#pragma unroll
    for (int i = 0; i < 4; i++) {
        m_r[i] = -1e30f; l_r[i] = 0.f;
#pragma unroll
        for (int j = 0; j < 4; j++) accO2[i][j] = 0ull;
    }
    const float scale = 0.125f;

    for (int nt = 0; nt < S_LEN / 64; ++nt) {
        __syncthreads();
#pragma unroll
        for (int it = 0; it < 4; ++it) {
            int i = tid + it * 256;
            int r = i >> 4, c = i & 15;
            *(float4*)&Kt[r][c * 4] =
                *(const float4*)&Kg[(size_t)r * S_LEN + nt * 64 + c * 4];
            *(float4*)&Vs[r][c * 4] =
                *(const float4*)&Vg[(size_t)(nt * 64 + r) * (3 * DIM) + c * 4];
        }
        __syncthreads();

        ull s2[4][4];
#pragma unroll
        for (int i = 0; i < 4; i++)
#pragma unroll
            for (int j = 0; j < 4; j++) s2[i][j] = 0ull;
#pragma unroll 8
        for (int d = 0; d < 64; ++d) {
            float4 a = *(const float4*)&Qt[d][ty * 4];
            ulonglong2 b0 = *(const ulonglong2*)&Kt[d][tx * 8];
            ulonglong2 b1 = *(const ulonglong2*)&Kt[d][tx * 8 + 4];
            ull bv[4] = {b0.x, b0.y, b1.x, b1.y};
            ull ad[4] = {pkdup(a.x), pkdup(a.y), pkdup(a.z), pkdup(a.w)};
#pragma unroll
            for (int i = 0; i < 4; i++)
#pragma unroll
                for (int j = 0; j < 4; j++) fma2(s2[i][j], ad[i], bv[j]);
        }

#pragma unroll
        for (int i = 0; i < 4; i++) {
            float2 t0 = unpk(s2[i][0]), t1 = unpk(s2[i][1]);
            float2 t2 = unpk(s2[i][2]), t3 = unpk(s2[i][3]);
            float sv[8] = {t0.x, t0.y, t1.x, t1.y, t2.x, t2.y, t3.x, t3.y};
            float mt = -1e30f;
#pragma unroll
            for (int j = 0; j < 8; j++) { sv[j] *= scale; mt = fmaxf(mt, sv[j]); }
            mt = fmaxf(mt, __shfl_xor_sync(0xffffffffu, mt, 1));
            mt = fmaxf(mt, __shfl_xor_sync(0xffffffffu, mt, 2));
            mt = fmaxf(mt, __shfl_xor_sync(0xffffffffu, mt, 16));
            float mn = fmaxf(m_r[i], mt);
            float alpha = __expf(m_r[i] - mn);
            float rs = 0.f;
            float p[8];
#pragma unroll
            for (int j = 0; j < 8; j++) { p[j] = __expf(sv[j] - mn); rs += p[j]; }
            *(float4*)&Ps[ty * 4 + i][tx * 8]     = make_float4(p[0], p[1], p[2], p[3]);
            *(float4*)&Ps[ty * 4 + i][tx * 8 + 4] = make_float4(p[4], p[5], p[6], p[7]);
            rs += __shfl_xor_sync(0xffffffffu, rs, 1);
            rs += __shfl_xor_sync(0xffffffffu, rs, 2);
            rs += __shfl_xor_sync(0xffffffffu, rs, 16);
            l_r[i] = l_r[i] * alpha + rs;
            m_r[i] = mn;
            ull al2 = pkdup(alpha);
#pragma unroll
            for (int j = 0; j < 4; j++) mul2(accO2[i][j], al2);
        }
        __syncthreads();

#pragma unroll 8
        for (int j = 0; j < 64; ++j) {
            ulonglong2 v0 = *(const ulonglong2*)&Vs[j][tx * 8];
            ulonglong2 v1 = *(const ulonglong2*)&Vs[j][tx * 8 + 4];
            ull vb[4] = {v0.x, v0.y, v1.x, v1.y};
#pragma unroll
            for (int i = 0; i < 4; i++) {
                ull pd = pkdup(Ps[ty * 4 + i][j]);
#pragma unroll
                for (int c = 0; c < 4; c++) fma2(accO2[i][c], pd, vb[c]);
            }
        }
    }

    // write O as bf16 hi/lo (proj GEMM input)
#pragma unroll
    for (int i = 0; i < 4; i++) {
        float inv = 1.f / l_r[i];
        int row = b * S_LEN + qt * 128 + ty * 4 + i;
        size_t off = (size_t)row * DIM + h * HD + tx * 8;
        float2 u0 = unpk(accO2[i][0]), u1 = unpk(accO2[i][1]);
        float2 u2 = unpk(accO2[i][2]), u3 = unpk(accO2[i][3]);
        float ov[8] = {u0.x * inv, u0.y * inv, u1.x * inv, u1.y * inv,
                       u2.x * inv, u2.y * inv, u3.x * inv, u3.y * inv};
#pragma unroll
        for (int j = 0; j < 8; j++) {
            __nv_bfloat16 hv, lv; split_bf16(ov[j], hv, lv);
            outh[off + j] = hv;
            outl[off + j] = lv;
        }
    }
}

// ---------------- launcher ----------------
extern "C" void kernel_launch(void* const* d_in, const int* in_sizes, int n_in,
                              void* d_out, int out_size)
{
    const float* x        = (const float*)d_in[0];
    const float* rope_cos = (const float*)d_in[1];
    const float* rope_sin = (const float*)d_in[2];
    const float* n1g      = (const float*)d_in[3];
    const float* n1b      = (const float*)d_in[4];
    const float* n2g      = (const float*)d_in[5];
    const float* n2b      = (const float*)d_in[6];
    const float* w_qkv    = (const float*)d_in[7];
    const float* b_qkv    = (const float*)d_in[8];
    const float* w_proj   = (const float*)d_in[9];
    const float* b_proj   = (const float*)d_in[10];
    const float* w_fc1    = (const float*)d_in[11];
    const float* b_fc1    = (const float*)d_in[12];
    const float* w_fc2    = (const float*)d_in[13];
    const float* b_fc2    = (const float*)d_in[14];
    float* out = (float*)d_out;

    __nv_bfloat16 *phh, *phl, *patth, *pattl, *pmidh, *pmidl;
    __nv_bfloat16 *wqh, *wql, *wph, *wpl, *w1h, *w1l, *w2h, *w2l;
    float *pqkv, *pqt, *pkt, *px1;
    cudaGetSymbolAddress((void**)&phh,   g_hh);
    cudaGetSymbolAddress((void**)&phl,   g_hl);
    cudaGetSymbolAddress((void**)&pqkv,  g_qkv);
    cudaGetSymbolAddress((void**)&pqt,   g_qt);
    cudaGetSymbolAddress((void**)&pkt,   g_kt);
    cudaGetSymbolAddress((void**)&patth, g_atth);
    cudaGetSymbolAddress((void**)&pattl, g_attl);
    cudaGetSymbolAddress((void**)&px1,   g_x1);
    cudaGetSymbolAddress((void**)&pmidh, g_midh);
    cudaGetSymbolAddress((void**)&pmidl, g_midl);
    cudaGetSymbolAddress((void**)&wqh, g_wqkvh);
    cudaGetSymbolAddress((void**)&wql, g_wqkvl);
    cudaGetSymbolAddress((void**)&wph, g_wprojh);
    cudaGetSymbolAddress((void**)&wpl, g_wprojl);
    cudaGetSymbolAddress((void**)&w1h, g_wfc1h);
    cudaGetSymbolAddress((void**)&w1l, g_wfc1l);
    cudaGetSymbolAddress((void**)&w2h, g_wfc2h);
    cudaGetSymbolAddress((void**)&w2l, g_wfc2l);

    cudaFuncSetAttribute(attn_kernel, cudaFuncAttributeMaxDynamicSharedMemorySize,
                         ATT_SMEM_FLOATS * (int)sizeof(float));

    // 0) weight transpose + bf16 split (W[K][N] -> [N][K] hi/lo)
    wsplit<<<dim3(3 * DIM / 32, DIM / 32), 256>>>(w_qkv,  wqh, wql, DIM,     3 * DIM);
    wsplit<<<dim3(DIM / 32,     DIM / 32), 256>>>(w_proj, wph, wpl, DIM,     DIM);
    wsplit<<<dim3(4 * DIM / 32, DIM / 32), 256>>>(w_fc1,  w1h, w1l, DIM,     4 * DIM);
    wsplit<<<dim3(DIM / 32, 4 * DIM / 32), 256>>>(w_fc2,  w2h, w2l, 4 * DIM, DIM);

    // 1) LN1 -> bf16 hi/lo
    ln_kernel<<<TOK, 256>>>(x, n1g, n1b, phh, phl);
    // 2) QKV GEMM (mma.sync) -> fp32 qkv
    mma_gemm<0,0><<<dim3(3 * DIM / 128, TOK / 128), 256>>>(
        phh, phl, wqh, wql, b_qkv, nullptr, pqkv, nullptr, nullptr, TOK, 3 * DIM, DIM);
    // 3) RoPE + transpose
    qk_rope_transpose<<<dim3(S_LEN / 32, NB * NH), 256>>>(pqkv, rope_cos, rope_sin, pqt, pkt);
    // 4) attention -> bf16 hi/lo
    attn_kernel<<<dim3(S_LEN / 128, NH, NB), 256, ATT_SMEM_FLOATS * sizeof(float)>>>(
        pqt, pkt, pqkv, patth, pattl);
    // 5) proj + bias + residual(x) -> x1 fp32
    mma_gemm<2,0><<<dim3(DIM / 128, TOK / 128), 256>>>(
        patth, pattl, wph, wpl, b_proj, x, px1, nullptr, nullptr, TOK, DIM, DIM);
    // 6) LN2 -> bf16 hi/lo
    ln_kernel<<<TOK, 256>>>(px1, n2g, n2b, phh, phl);
    // 7) FC1 + bias + GELU -> bf16 hi/lo
    mma_gemm<1,1><<<dim3(4 * DIM / 128, TOK / 128), 256>>>(
        phh, phl, w1h, w1l, b_fc1, nullptr, nullptr, pmidh, pmidl, TOK, 4 * DIM, DIM);
    // 8) FC2 + bias + residual(x1) -> out fp32
    mma_gemm<2,0><<<dim3(DIM / 128, TOK / 128), 256>>>(
        pmidh, pmidl, w2h, w2l, b_fc2, px1, out, nullptr, nullptr, TOK, DIM, 4 * DIM);
}

// round 16
// speedup vs baseline: 2.7924x; 1.9585x over previous
#include <cuda_runtime.h>
#include <cuda_bf16.h>
#include <math.h>
#include <stdint.h>

// ---------------- problem constants ----------------
#define NB    4
#define S_LEN 2048
#define DIM   512
#define NH    8
#define HD    64
#define TOK   (NB * S_LEN)          // 8192

typedef unsigned long long ull;

// ---- packed f32x2 helpers ----
__device__ __forceinline__ ull pk2(float a, float b)
{
    ull r; asm("mov.b64 %0, {%1, %2};" : "=l"(r) : "f"(a), "f"(b)); return r;
}
__device__ __forceinline__ ull pkdup(float a) { return pk2(a, a); }
__device__ __forceinline__ float2 unpk(ull v)
{
    float2 r; asm("mov.b64 {%0, %1}, %2;" : "=f"(r.x), "=f"(r.y) : "l"(v)); return r;
}
__device__ __forceinline__ ull fma2v(ull a, ull b, ull c)
{
    ull d; asm("fma.rn.f32x2 %0, %1, %2, %3;" : "=l"(d) : "l"(a), "l"(b), "l"(c)); return d;
}
__device__ __forceinline__ ull add2v(ull a, ull b)
{
    ull d; asm("add.rn.f32x2 %0, %1, %2;" : "=l"(d) : "l"(a), "l"(b)); return d;
}
__device__ __forceinline__ ull mul2v(ull a, ull b)
{
    ull d; asm("mul.rn.f32x2 %0, %1, %2;" : "=l"(d) : "l"(a), "l"(b)); return d;
}

// ---- mma.sync helpers (baseline PTX, compiles under compute_103) ----
__device__ __forceinline__ uint32_t smem_u32(const void* p)
{
    uint32_t a;
    asm("{ .reg .u64 t; cvta.to.shared.u64 t, %1; cvt.u32.u64 %0, t; }"
        : "=r"(a) : "l"(p));
    return a;
}
__device__ __forceinline__ void ldsm_x4(uint32_t* r, uint32_t addr)
{
    asm volatile("ldmatrix.sync.aligned.m8n8.x4.shared.b16 {%0,%1,%2,%3}, [%4];"
                 : "=r"(r[0]), "=r"(r[1]), "=r"(r[2]), "=r"(r[3]) : "r"(addr));
}
__device__ __forceinline__ void ldsm_x4t(uint32_t* r, uint32_t addr)
{
    asm volatile("ldmatrix.sync.aligned.m8n8.x4.trans.shared.b16 {%0,%1,%2,%3}, [%4];"
                 : "=r"(r[0]), "=r"(r[1]), "=r"(r[2]), "=r"(r[3]) : "r"(addr));
}
__device__ __forceinline__ void mma16816(float* d, const uint32_t* a, const uint32_t* b)
{
    asm volatile("mma.sync.aligned.m16n8k16.row.col.f32.bf16.bf16.f32 "
                 "{%0,%1,%2,%3}, {%4,%5,%6,%7}, {%8,%9}, {%0,%1,%2,%3};"
                 : "+f"(d[0]), "+f"(d[1]), "+f"(d[2]), "+f"(d[3])
                 : "r"(a[0]), "r"(a[1]), "r"(a[2]), "r"(a[3]), "r"(b[0]), "r"(b[1]));
}
__device__ __forceinline__ uint32_t cvt_bf16x2(float hi, float lo)
{
    uint32_t r;
    asm("cvt.rn.bf16x2.f32 %0, %1, %2;" : "=r"(r) : "f"(hi), "f"(lo));
    return r;
}

// packed exp2-based exp: p_i = exp(s_i - mn) given nm2 = pkdup(-mn*log2e)
__device__ __forceinline__ void exp2pk(ull s2, ull nm2, float& p0, float& p1)
{
    const ull L2E2  = pkdup(1.4426950408889634f);
    const ull MAG2  = pkdup(12582912.0f);
    const ull NMAG2 = pkdup(-12582912.0f);
    const ull NEG12 = pkdup(-1.0f);
    const ull C4 = pkdup(0.009618130f);
    const ull C3 = pkdup(0.055504110f);
    const ull C2 = pkdup(0.240226507f);
    const ull C1 = pkdup(0.693147181f);
    const ull C0 = pkdup(1.0f);
    ull y2  = fma2v(s2, L2E2, nm2);
    ull t2  = add2v(y2, MAG2);
    ull nf2 = add2v(t2, NMAG2);
    ull f2  = fma2v(nf2, NEG12, y2);
    ull q2  = fma2v(f2, C4, C3);
    q2 = fma2v(f2, q2, C2);
    q2 = fma2v(f2, q2, C1);
    q2 = fma2v(f2, q2, C0);
    float2 tf = unpk(t2);
    int i0 = __float_as_int(tf.x), i1 = __float_as_int(tf.y);
    const int LOW = 0x4B400000 - 126;
    i0 = i0 < LOW ? LOW : i0;
    i1 = i1 < LOW ? LOW : i1;
    float sc0 = __int_as_float((i0 << 23) + 0x3f800000);
    float sc1 = __int_as_float((i1 << 23) + 0x3f800000);
    float2 pf = unpk(mul2v(q2, pk2(sc0, sc1)));
    p0 = pf.x; p1 = pf.y;
}

// ---------------- scratch (no allocations allowed) ----------------
__device__ __nv_bfloat16 g_hh[TOK * DIM],  g_hl[TOK * DIM];     // LN out hi/lo
__device__ float g_qkv[TOK * 3 * DIM];
__device__ __nv_bfloat16 g_qh[NB * NH * S_LEN * HD];            // roped Q (pre-scaled) bf16
__device__ __nv_bfloat16 g_kh[NB * NH * S_LEN * HD];            // roped K bf16
__device__ __nv_bfloat16 g_vh[NB * NH * S_LEN * HD];            // V bf16
__device__ __nv_bfloat16 g_atth[TOK * DIM], g_attl[TOK * DIM];  // attention out hi/lo
__device__ float g_x1[TOK * DIM];
__device__ __nv_bfloat16 g_midh[TOK * 4 * DIM], g_midl[TOK * 4 * DIM];
__device__ __nv_bfloat16 g_wqkvh[3 * DIM * DIM], g_wqkvl[3 * DIM * DIM];
__device__ __nv_bfloat16 g_wprojh[DIM * DIM],    g_wprojl[DIM * DIM];
__device__ __nv_bfloat16 g_wfc1h[4 * DIM * DIM], g_wfc1l[4 * DIM * DIM];
__device__ __nv_bfloat16 g_wfc2h[4 * DIM * DIM], g_wfc2l[4 * DIM * DIM];

__device__ __forceinline__ void split_bf16(float v, __nv_bfloat16& hi, __nv_bfloat16& lo)
{
    hi = __float2bfloat16(v);
    lo = __float2bfloat16(v - __bfloat162float(hi));
}

// ---------------- weight transpose + split ----------------
__global__ void __launch_bounds__(256) wsplit(const float* __restrict__ W,
                                              __nv_bfloat16* __restrict__ th,
                                              __nv_bfloat16* __restrict__ tl,
                                              int K, int N)
{
    __shared__ float t[32][33];
    int n0 = blockIdx.x * 32, k0 = blockIdx.y * 32;
    int j = threadIdx.x & 31, i0 = threadIdx.x >> 5;
#pragma unroll
    for (int it = 0; it < 4; it++) {
        int i = i0 + it * 8;
        t[i][j] = W[(size_t)(k0 + i) * N + n0 + j];
    }
    __syncthreads();
#pragma unroll
    for (int it = 0; it < 4; it++) {
        int i = i0 + it * 8;
        float v = t[j][i];
        __nv_bfloat16 hv, lv; split_bf16(v, hv, lv);
        size_t o = (size_t)(n0 + i) * K + k0 + j;
        th[o] = hv; tl[o] = lv;
    }
}

// ---------------- LayerNorm -> bf16 hi/lo ----------------
__global__ void __launch_bounds__(256) ln_kernel(const float* __restrict__ x,
                                                 const float* __restrict__ g,
                                                 const float* __restrict__ b,
                                                 __nv_bfloat16* __restrict__ oh,
                                                 __nv_bfloat16* __restrict__ ol)
{
    int row = blockIdx.x;
    int t = threadIdx.x;
    const float2* xr = (const float2*)(x + (size_t)row * DIM);
    float2 v = xr[t];
    float s = v.x + v.y;
    float ss = v.x * v.x + v.y * v.y;
#pragma unroll
    for (int m = 16; m; m >>= 1) {
        s  += __shfl_xor_sync(0xffffffffu, s, m);
        ss += __shfl_xor_sync(0xffffffffu, ss, m);
    }
    __shared__ float sh[16];
    int w = t >> 5;
    if ((t & 31) == 0) { sh[w] = s; sh[8 + w] = ss; }
    __syncthreads();
    s = 0.f; ss = 0.f;
#pragma unroll
    for (int i = 0; i < 8; i++) { s += sh[i]; ss += sh[8 + i]; }
    float mu  = s * (1.f / DIM);
    float var = ss * (1.f / DIM) - mu * mu;
    float inv = rsqrtf(var + 1e-5f);
    float2 gg = ((const float2*)g)[t];
    float2 bb = ((const float2*)b)[t];
    float vx = (v.x - mu) * inv * gg.x + bb.x;
    float vy = (v.y - mu) * inv * gg.y + bb.y;
    size_t idx = (size_t)row * DIM + 2 * t;
    __nv_bfloat16 h0, l0, h1, l1;
    split_bf16(vx, h0, l0); split_bf16(vy, h1, l1);
    oh[idx] = h0; oh[idx + 1] = h1;
    ol[idx] = l0; ol[idx + 1] = l1;
}

// ---------------- RoPE + bf16 convert: qkv fp32 -> qh (x0.125), kh, vh [bh][s][d] ----------------
__global__ void __launch_bounds__(256) rope_bf16(const float* __restrict__ qkv,
                                                 const float* __restrict__ cb,
                                                 const float* __restrict__ sb,
                                                 __nv_bfloat16* __restrict__ qh,
                                                 __nv_bfloat16* __restrict__ kh,
                                                 __nv_bfloat16* __restrict__ vh)
{
    int t = blockIdx.x * blockDim.x + threadIdx.x;   // TOK*NH*32
    int d = t & 31, hh = (t >> 5) & 7, tok = t >> 8;
    int s = tok & (S_LEN - 1), b = tok >> 11;
    int bh = b * NH + hh;
    const float* row = qkv + (size_t)tok * (3 * DIM);
    float c0 = cb[s * HD + d], c1 = cb[s * HD + d + 32];
    float s0 = sb[s * HD + d], s1 = sb[s * HD + d + 32];
    float q0 = row[hh * HD + d],        q1 = row[hh * HD + d + 32];
    float k0 = row[DIM + hh * HD + d],  k1 = row[DIM + hh * HD + d + 32];
    float v0 = row[2 * DIM + hh * HD + d], v1 = row[2 * DIM + hh * HD + d + 32];
    float rq0 = (q0 * c0 - q1 * s0) * 0.125f;
    float rq1 = (q1 * c1 + q0 * s1) * 0.125f;
    float rk0 = k0 * c0 - k1 * s0;
    float rk1 = k1 * c1 + k0 * s1;
    size_t o = ((size_t)bh * S_LEN + s) * HD + d;
    qh[o] = __float2bfloat16(rq0); qh[o + 32] = __float2bfloat16(rq1);
    kh[o] = __float2bfloat16(rk0); kh[o + 32] = __float2bfloat16(rk1);
    vh[o] = __float2bfloat16(v0);  vh[o + 32] = __float2bfloat16(v1);
}

// ---------------- mma.sync bf16x3 GEMM (R15, unchanged) ----------------
__device__ __forceinline__ float gelu_f(float x)
{
    return 0.5f * x * (1.f + erff(x * 0.7071067811865476f));
}

#define GPAD 40

template <int EPI, int OUT>
__global__ void __launch_bounds__(256) mma_gemm(const __nv_bfloat16* __restrict__ Ah,
                                                const __nv_bfloat16* __restrict__ Al,
                                                const __nv_bfloat16* __restrict__ Bh,
                                                const __nv_bfloat16* __restrict__ Bl,
                                                const float* __restrict__ bias,
                                                const float* __restrict__ R,
                                                float* __restrict__ C,
                                                __nv_bfloat16* __restrict__ Ch,
                                                __nv_bfloat16* __restrict__ Cl,
                                                int M, int N, int K)
{
    __shared__ __align__(16) __nv_bfloat16 sAh[128 * GPAD], sAl[128 * GPAD];
    __shared__ __align__(16) __nv_bfloat16 sBh[128 * GPAD], sBl[128 * GPAD];

    int tid = threadIdx.x, lane = tid & 31, wid = tid >> 5;
    int wm = wid & 3, wn = wid >> 2;
    int m0 = blockIdx.y * 128, n0 = blockIdx.x * 128;

    uint32_t uAh = smem_u32(sAh), uAl = smem_u32(sAl);
    uint32_t uBh = smem_u32(sBh), uBl = smem_u32(sBl);

    uint32_t aoff = (uint32_t)((lane & 15) * GPAD + (lane >> 4) * 8) * 2;
    uint32_t boff = (uint32_t)((((lane >> 4) & 1) * 8 + (lane & 7)) * GPAD +
                               ((lane >> 3) & 1) * 8) * 2;

    float acc[2][8][4];
#pragma unroll
    for (int i = 0; i < 2; i++)
#pragma unroll
        for (int j = 0; j < 8; j++)
#pragma unroll
            for (int c = 0; c < 4; c++) acc[i][j][c] = 0.f;

    for (int kk = 0; kk < K; kk += 32) {
#pragma unroll
        for (int it = 0; it < 2; ++it) {
            int u = tid + it * 256;
            int r = u >> 2, sg = u & 3;
            size_t ga = (size_t)(m0 + r) * K + kk + sg * 8;
            size_t gb = (size_t)(n0 + r) * K + kk + sg * 8;
            int so = r * GPAD + sg * 8;
            *(uint4*)&sAh[so] = *(const uint4*)&Ah[ga];
            *(uint4*)&sAl[so] = *(const uint4*)&Al[ga];
            *(uint4*)&sBh[so] = *(const uint4*)&Bh[gb];
            *(uint4*)&sBl[so] = *(const uint4*)&Bl[gb];
        }
        __syncthreads();

#pragma unroll
        for (int k16 = 0; k16 < 2; ++k16) {
            uint32_t kb = (uint32_t)(k16 * 16 * 2);
            uint32_t ah[2][4], al[2][4];
#pragma unroll
            for (int mt = 0; mt < 2; ++mt) {
                uint32_t ro = (uint32_t)((wm * 32 + mt * 16) * GPAD * 2) + kb + aoff;
                ldsm_x4(ah[mt], uAh + ro);
                ldsm_x4(al[mt], uAl + ro);
            }
            uint32_t bh[4][4], bl[4][4];
#pragma unroll
            for (int p = 0; p < 4; ++p) {
                uint32_t ro = (uint32_t)((wn * 64 + p * 16) * GPAD * 2) + kb + boff;
                ldsm_x4(bh[p], uBh + ro);
                ldsm_x4(bl[p], uBl + ro);
            }
#pragma unroll
            for (int mt = 0; mt < 2; ++mt)
#pragma unroll
                for (int nt = 0; nt < 8; ++nt) {
                    const uint32_t* fh = &bh[nt >> 1][(nt & 1) * 2];
                    const uint32_t* fl = &bl[nt >> 1][(nt & 1) * 2];
                    mma16816(acc[mt][nt], ah[mt], fh);
                    mma16816(acc[mt][nt], ah[mt], fl);
                    mma16816(acc[mt][nt], al[mt], fh);
                }
        }
        __syncthreads();
    }

#pragma unroll
    for (int mt = 0; mt < 2; ++mt) {
#pragma unroll
        for (int nt = 0; nt < 8; ++nt) {
            int row = m0 + wm * 32 + mt * 16 + (lane >> 2);
            int col = n0 + wn * 64 + nt * 8 + (lane & 3) * 2;
            float b0 = bias[col], b1 = bias[col + 1];
#pragma unroll
            for (int half = 0; half < 2; ++half) {
                int r = row + half * 8;
                float v0 = acc[mt][nt][half * 2 + 0] + b0;
                float v1 = acc[mt][nt][half * 2 + 1] + b1;
                if (EPI == 1) { v0 = gelu_f(v0); v1 = gelu_f(v1); }
                size_t off = (size_t)r * N + col;
                if (EPI == 2) {
                    float2 rr = *(const float2*)&R[off];
                    v0 += rr.x; v1 += rr.y;
                }
                if (OUT == 0) {
                    *(float2*)&C[off] = make_float2(v0, v1);
                } else {
                    __nv_bfloat16 h0, l0, h1, l1;
                    split_bf16(v0, h0, l0); split_bf16(v1, h1, l1);
                    *(__nv_bfloat162*)&Ch[off] = __nv_bfloat162(h0, h1);
                    *(__nv_bfloat162*)&Cl[off] = __nv_bfloat162(l0, l1);
                }
            }
        }
    }
}

// ---------------- tensor-core flash attention + hybrid exp ----------------
// grid (S/128, NH, NB), 256 thr (8 warps x 16 q-rows). Key tile = 64.
// Qs[128][72], Ks[64][72], Vs[64][72] bf16, pitch 72 (conflict-free ldmatrix).
#define APITCH 72

__global__ void __launch_bounds__(256) attn_kernel(const __nv_bfloat16* __restrict__ qh,
                                                   const __nv_bfloat16* __restrict__ kh,
                                                   const __nv_bfloat16* __restrict__ vh,
                                                   __nv_bfloat16* __restrict__ oh,
                                                   __nv_bfloat16* __restrict__ ol)
{
    __shared__ __align__(16) __nv_bfloat16 Qs[128 * APITCH];
    __shared__ __align__(16) __nv_bfloat16 Ks[64 * APITCH];
    __shared__ __align__(16) __nv_bfloat16 Vs[64 * APITCH];

    int tid = threadIdx.x, lane = tid & 31, w = tid >> 5;
    int qt = blockIdx.x, h = blockIdx.y, b = blockIdx.z;
    int bh = b * NH + h;

    const __nv_bfloat16* Qg = qh + ((size_t)bh * S_LEN + qt * 128) * HD;
    const __nv_bfloat16* Kg = kh + (size_t)bh * S_LEN * HD;
    const __nv_bfloat16* Vg = vh + (size_t)bh * S_LEN * HD;

    // stage Q (128 x 64 bf16)
#pragma unroll
    for (int it = 0; it < 4; ++it) {
        int u = tid + it * 256;
        int r = u >> 3, sg = u & 7;
        *(uint4*)&Qs[r * APITCH + sg * 8] = *(const uint4*)&Qg[r * HD + sg * 8];
    }
    __syncthreads();

    uint32_t uQ = smem_u32(Qs), uK = smem_u32(Ks), uV = smem_u32(Vs);

    // Q fragments: warp w rows [w*16, +16), 4 k-chunks of 16 d
    uint32_t aq[4][4];
    {
        uint32_t row = (uint32_t)(w * 16 + (lane & 15));
        uint32_t segb = (uint32_t)((lane >> 4) << 3);
#pragma unroll
        for (int kc = 0; kc < 4; ++kc)
            ldsm_x4(aq[kc], uQ + 2u * (row * APITCH + kc * 16 + segb));
    }

    uint32_t kboff = 2u * ((((lane >> 4) & 1) * 8 + (lane & 7)) * APITCH + ((lane >> 3) & 1) * 8);
    uint32_t vboff = 2u * ((((lane >> 3) & 1) * 8 + (lane & 7)) * APITCH + ((lane >> 4) & 1) * 8);

    float o[8][4];
#pragma unroll
    for (int a = 0; a < 8; a++)
#pragma unroll
        for (int c = 0; c < 4; c++) o[a][c] = 0.f;
    float mA = -1e30f, mB = -1e30f, lA = 0.f, lB = 0.f;
    const float L2E = 1.4426950408889634f;

    for (int nt = 0; nt < S_LEN / 64; ++nt) {
        __syncthreads();
#pragma unroll
        for (int it = 0; it < 2; ++it) {
            int u = tid + it * 256;
            int r = u >> 3, sg = u & 7;
            *(uint4*)&Ks[r * APITCH + sg * 8] = *(const uint4*)&Kg[(nt * 64 + r) * HD + sg * 8];
            *(uint4*)&Vs[r * APITCH + sg * 8] = *(const uint4*)&Vg[(nt * 64 + r) * HD + sg * 8];
        }
        __syncthreads();

        // S = Q K^T : warp computes 16 x 64 in 8 atoms
        float sf[8][4];
#pragma unroll
        for (int a = 0; a < 8; a++)
#pragma unroll
            for (int c = 0; c < 4; c++) sf[a][c] = 0.f;
#pragma unroll
        for (int kc = 0; kc < 4; ++kc) {
            uint32_t bk[4][4];
#pragma unroll
            for (int np = 0; np < 4; ++np)
                ldsm_x4(bk[np], uK + kboff + 2u * (np * 16 * APITCH + kc * 16));
#pragma unroll
            for (int np = 0; np < 4; ++np) {
                mma16816(sf[2 * np],     aq[kc], &bk[np][0]);
                mma16816(sf[2 * np + 1], aq[kc], &bk[np][2]);
            }
        }

        // online softmax (rows A = lane>>2, B = +8); quad shuffles masks 1,2
        float txA = -1e30f, txB = -1e30f;
#pragma unroll
        for (int a = 0; a < 8; a++) {
            txA = fmaxf(txA, fmaxf(sf[a][0], sf[a][1]));
            txB = fmaxf(txB, fmaxf(sf[a][2], sf[a][3]));
        }
        txA = fmaxf(txA, __shfl_xor_sync(0xffffffffu, txA, 1));
        txA = fmaxf(txA, __shfl_xor_sync(0xffffffffu, txA, 2));
        txB = fmaxf(txB, __shfl_xor_sync(0xffffffffu, txB, 1));
        txB = fmaxf(txB, __shfl_xor_sync(0xffffffffu, txB, 2));
        float mnA = fmaxf(mA, txA), mnB = fmaxf(mB, txB);
        float aAl = __expf(mA - mnA), aBl = __expf(mB - mnB);
        mA = mnA; mB = mnB;
        ull nmA2 = pkdup(-mnA * L2E), nmB2 = pkdup(-mnB * L2E);
        float sA = 0.f, sB = 0.f;
#pragma unroll
        for (int a = 0; a < 8; a++) {
            if (a & 1) {   // MUFU path
                sf[a][0] = __expf(sf[a][0] - mnA);
                sf[a][1] = __expf(sf[a][1] - mnA);
                sf[a][2] = __expf(sf[a][2] - mnB);
                sf[a][3] = __expf(sf[a][3] - mnB);
            } else {       // packed fma poly path
                exp2pk(pk2(sf[a][0], sf[a][1]), nmA2, sf[a][0], sf[a][1]);
                exp2pk(pk2(sf[a][2], sf[a][3]), nmB2, sf[a][2], sf[a][3]);
            }
            sA += sf[a][0] + sf[a][1];
            sB += sf[a][2] + sf[a][3];
        }
        sA += __shfl_xor_sync(0xffffffffu, sA, 1);
        sA += __shfl_xor_sync(0xffffffffu, sA, 2);
        sB += __shfl_xor_sync(0xffffffffu, sB, 1);
        sB += __shfl_xor_sync(0xffffffffu, sB, 2);
        lA = lA * aAl + sA;
        lB = lB * aBl + sB;
#pragma unroll
        for (int a = 0; a < 8; a++) {
            o[a][0] *= aAl; o[a][1] *= aAl;
            o[a][2] *= aBl; o[a][3] *= aBl;
        }

        // O += P V : P fragments come straight from sf registers
#pragma unroll
        for (int kc = 0; kc < 4; ++kc) {
            uint32_t bv[4][4];
#pragma unroll
            for (int np = 0; np < 4; ++np)
                ldsm_x4t(bv[np], uV + vboff + 2u * (kc * 16 * APITCH + np * 16));
            uint32_t pa[4];
            pa[0] = cvt_bf16x2(sf[2 * kc][1],     sf[2 * kc][0]);
            pa[1] = cvt_bf16x2(sf[2 * kc][3],     sf[2 * kc][2]);
            pa[2] = cvt_bf16x2(sf[2 * kc + 1][1], sf[2 * kc + 1][0]);
            pa[3] = cvt_bf16x2(sf[2 * kc + 1][3], sf[2 * kc + 1][2]);
#pragma unroll
            for (int np = 0; np < 4; ++np) {
                mma16816(o[2 * np],     pa, &bv[np][0]);
                mma16816(o[2 * np + 1], pa, &bv[np][2]);
            }
        }
    }

    // epilogue: normalize, split hi/lo, write (b,s,h*64+d)
    float iA = 1.f / lA, iB = 1.f / lB;
    int rA = b * S_LEN + qt * 128 + w * 16 + (lane >> 2);
    int rB = rA + 8;
    int cb0 = h * HD + (lane & 3) * 2;
#pragma unroll
    for (int a = 0; a < 8; a++) {
        int col = cb0 + a * 8;
        float v0 = o[a][0] * iA, v1 = o[a][1] * iA;
        float v2 = o[a][2] * iB, v3 = o[a][3] * iB;
        __nv_bfloat16 h0, l0, h1, l1, h2, l2, h3, l3;
        split_bf16(v0, h0, l0); split_bf16(v1, h1, l1);
        split_bf16(v2, h2, l2); split_bf16(v3, h3, l3);
        *(__nv_bfloat162*)&oh[(size_t)rA * DIM + col] = __nv_bfloat162(h0, h1);
        *(__nv_bfloat162*)&ol[(size_t)rA * DIM + col] = __nv_bfloat162(l0, l1);
        *(__nv_bfloat162*)&oh[(size_t)rB * DIM + col] = __nv_bfloat162(h2, h3);
        *(__nv_bfloat162*)&ol[(size_t)rB * DIM + col] = __nv_bfloat162(l2, l3);
    }
}

// ---------------- launcher ----------------
extern "C" void kernel_launch(void* const* d_in, const int* in_sizes, int n_in,
                              void* d_out, int out_size)
{
    const float* x        = (const float*)d_in[0];
    const float* rope_cos = (const float*)d_in[1];
    const float* rope_sin = (const float*)d_in[2];
    const float* n1g      = (const float*)d_in[3];
    const float* n1b      = (const float*)d_in[4];
    const float* n2g      = (const float*)d_in[5];
    const float* n2b      = (const float*)d_in[6];
    const float* w_qkv    = (const float*)d_in[7];
    const float* b_qkv    = (const float*)d_in[8];
    const float* w_proj   = (const float*)d_in[9];
    const float* b_proj   = (const float*)d_in[10];
    const float* w_fc1    = (const float*)d_in[11];
    const float* b_fc1    = (const float*)d_in[12];
    const float* w_fc2    = (const float*)d_in[13];
    const float* b_fc2    = (const float*)d_in[14];
    float* out = (float*)d_out;

    __nv_bfloat16 *phh, *phl, *patth, *pattl, *pmidh, *pmidl;
    __nv_bfloat16 *pqh, *pkh, *pvh;
    __nv_bfloat16 *wqh, *wql, *wph, *wpl, *w1h, *w1l, *w2h, *w2l;
    float *pqkv, *px1;
    cudaGetSymbolAddress((void**)&phh,   g_hh);
    cudaGetSymbolAddress((void**)&phl,   g_hl);
    cudaGetSymbolAddress((void**)&pqkv,  g_qkv);
    cudaGetSymbolAddress((void**)&pqh,   g_qh);
    cudaGetSymbolAddress((void**)&pkh,   g_kh);
    cudaGetSymbolAddress((void**)&pvh,   g_vh);
    cudaGetSymbolAddress((void**)&patth, g_atth);
    cudaGetSymbolAddress((void**)&pattl, g_attl);
    cudaGetSymbolAddress((void**)&px1,   g_x1);
    cudaGetSymbolAddress((void**)&pmidh, g_midh);
    cudaGetSymbolAddress((void**)&pmidl, g_midl);
    cudaGetSymbolAddress((void**)&wqh, g_wqkvh);
    cudaGetSymbolAddress((void**)&wql, g_wqkvl);
    cudaGetSymbolAddress((void**)&wph, g_wprojh);
    cudaGetSymbolAddress((void**)&wpl, g_wprojl);
    cudaGetSymbolAddress((void**)&w1h, g_wfc1h);
    cudaGetSymbolAddress((void**)&w1l, g_wfc1l);
    cudaGetSymbolAddress((void**)&w2h, g_wfc2h);
    cudaGetSymbolAddress((void**)&w2l, g_wfc2l);

    // 0) weight transpose + bf16 split
    wsplit<<<dim3(3 * DIM / 32, DIM / 32), 256>>>(w_qkv,  wqh, wql, DIM,     3 * DIM);
    wsplit<<<dim3(DIM / 32,     DIM / 32), 256>>>(w_proj, wph, wpl, DIM,     DIM);
    wsplit<<<dim3(4 * DIM / 32, DIM / 32), 256>>>(w_fc1,  w1h, w1l, DIM,     4 * DIM);
    wsplit<<<dim3(DIM / 32, 4 * DIM / 32), 256>>>(w_fc2,  w2h, w2l, 4 * DIM, DIM);

    // 1) LN1 -> bf16 hi/lo
    ln_kernel<<<TOK, 256>>>(x, n1g, n1b, phh, phl);
    // 2) QKV GEMM -> fp32 qkv
    mma_gemm<0,0><<<dim3(3 * DIM / 128, TOK / 128), 256>>>(
        phh, phl, wqh, wql, b_qkv, nullptr, pqkv, nullptr, nullptr, TOK, 3 * DIM, DIM);
    // 3) RoPE + bf16 convert (Q pre-scaled by 1/8)
    rope_bf16<<<(TOK * NH * 32) / 256, 256>>>(pqkv, rope_cos, rope_sin, pqh, pkh, pvh);
    // 4) tensor-core attention -> bf16 hi/lo
    attn_kernel<<<dim3(S_LEN / 128, NH, NB), 256>>>(pqh, pkh, pvh, patth, pattl);
    // 5) proj + bias + residual(x) -> x1 fp32
    mma_gemm<2,0><<<dim3(DIM / 128, TOK / 128), 256>>>(
        patth, pattl, wph, wpl, b_proj, x, px1, nullptr, nullptr, TOK, DIM, DIM);
    // 6) LN2 -> bf16 hi/lo
    ln_kernel<<<TOK, 256>>>(px1, n2g, n2b, phh, phl);
    // 7) FC1 + bias + GELU -> bf16 hi/lo
    mma_gemm<1,1><<<dim3(4 * DIM / 128, TOK / 128), 256>>>(
        phh, phl, w1h, w1l, b_fc1, nullptr, nullptr, pmidh, pmidl, TOK, 4 * DIM, DIM);
    // 8) FC2 + bias + residual(x1) -> out fp32
    mma_gemm<2,0><<<dim3(DIM / 128, TOK / 128), 256>>>(
        pmidh, pmidl, w2h, w2l, b_fc2, px1, out, nullptr, nullptr, TOK, DIM, 4 * DIM);
}

// round 17
// speedup vs baseline: 3.0983x; 1.1095x over previous
#include <cuda_runtime.h>
#include <cuda_bf16.h>
#include <math.h>
#include <stdint.h>

// ---------------- problem constants ----------------
#define NB    4
#define S_LEN 2048
#define DIM   512
#define NH    8
#define HD    64
#define TOK   (NB * S_LEN)          // 8192

typedef unsigned long long ull;

// ---- packed f32x2 helpers ----
__device__ __forceinline__ ull pk2(float a, float b)
{
    ull r; asm("mov.b64 %0, {%1, %2};" : "=l"(r) : "f"(a), "f"(b)); return r;
}
__device__ __forceinline__ ull pkdup(float a) { return pk2(a, a); }
__device__ __forceinline__ float2 unpk(ull v)
{
    float2 r; asm("mov.b64 {%0, %1}, %2;" : "=f"(r.x), "=f"(r.y) : "l"(v)); return r;
}
__device__ __forceinline__ ull fma2v(ull a, ull b, ull c)
{
    ull d; asm("fma.rn.f32x2 %0, %1, %2, %3;" : "=l"(d) : "l"(a), "l"(b), "l"(c)); return d;
}
__device__ __forceinline__ ull add2v(ull a, ull b)
{
    ull d; asm("add.rn.f32x2 %0, %1, %2;" : "=l"(d) : "l"(a), "l"(b)); return d;
}
__device__ __forceinline__ ull mul2v(ull a, ull b)
{
    ull d; asm("mul.rn.f32x2 %0, %1, %2;" : "=l"(d) : "l"(a), "l"(b)); return d;
}

// ---- mma.sync / cp.async helpers (baseline PTX, compiles under compute_103) ----
__device__ __forceinline__ uint32_t smem_u32(const void* p)
{
    uint32_t a;
    asm("{ .reg .u64 t; cvta.to.shared.u64 t, %1; cvt.u32.u64 %0, t; }"
        : "=r"(a) : "l"(p));
    return a;
}
__device__ __forceinline__ void ldsm_x4(uint32_t* r, uint32_t addr)
{
    asm volatile("ldmatrix.sync.aligned.m8n8.x4.shared.b16 {%0,%1,%2,%3}, [%4];"
                 : "=r"(r[0]), "=r"(r[1]), "=r"(r[2]), "=r"(r[3]) : "r"(addr));
}
__device__ __forceinline__ void ldsm_x4t(uint32_t* r, uint32_t addr)
{
    asm volatile("ldmatrix.sync.aligned.m8n8.x4.trans.shared.b16 {%0,%1,%2,%3}, [%4];"
                 : "=r"(r[0]), "=r"(r[1]), "=r"(r[2]), "=r"(r[3]) : "r"(addr));
}
__device__ __forceinline__ void mma16816(float* d, const uint32_t* a, const uint32_t* b)
{
    asm volatile("mma.sync.aligned.m16n8k16.row.col.f32.bf16.bf16.f32 "
                 "{%0,%1,%2,%3}, {%4,%5,%6,%7}, {%8,%9}, {%0,%1,%2,%3};"
                 : "+f"(d[0]), "+f"(d[1]), "+f"(d[2]), "+f"(d[3])
                 : "r"(a[0]), "r"(a[1]), "r"(a[2]), "r"(a[3]), "r"(b[0]), "r"(b[1]));
}
__device__ __forceinline__ uint32_t cvt_bf16x2(float hi, float lo)
{
    uint32_t r;
    asm("cvt.rn.bf16x2.f32 %0, %1, %2;" : "=r"(r) : "f"(hi), "f"(lo));
    return r;
}
__device__ __forceinline__ void cpa16(uint32_t dst, const void* src)
{
    asm volatile("cp.async.cg.shared.global [%0], [%1], 16;" :: "r"(dst), "l"(src));
}
#define CP_COMMIT() asm volatile("cp.async.commit_group;" ::: "memory")
#define CP_WAIT0()  asm volatile("cp.async.wait_group 0;" ::: "memory")

// packed exp2-based exp: p_i = exp(s_i - mn) given nm2 = pkdup(-mn*log2e)
__device__ __forceinline__ void exp2pk(ull s2, ull nm2, float& p0, float& p1)
{
    const ull L2E2  = pkdup(1.4426950408889634f);
    const ull MAG2  = pkdup(12582912.0f);
    const ull NMAG2 = pkdup(-12582912.0f);
    const ull NEG12 = pkdup(-1.0f);
    const ull C4 = pkdup(0.009618130f);
    const ull C3 = pkdup(0.055504110f);
    const ull C2 = pkdup(0.240226507f);
    const ull C1 = pkdup(0.693147181f);
    const ull C0 = pkdup(1.0f);
    ull y2  = fma2v(s2, L2E2, nm2);
    ull t2  = add2v(y2, MAG2);
    ull nf2 = add2v(t2, NMAG2);
    ull f2  = fma2v(nf2, NEG12, y2);
    ull q2  = fma2v(f2, C4, C3);
    q2 = fma2v(f2, q2, C2);
    q2 = fma2v(f2, q2, C1);
    q2 = fma2v(f2, q2, C0);
    float2 tf = unpk(t2);
    int i0 = __float_as_int(tf.x), i1 = __float_as_int(tf.y);
    const int LOW = 0x4B400000 - 126;
    i0 = i0 < LOW ? LOW : i0;
    i1 = i1 < LOW ? LOW : i1;
    float sc0 = __int_as_float((i0 << 23) + 0x3f800000);
    float sc1 = __int_as_float((i1 << 23) + 0x3f800000);
    float2 pf = unpk(mul2v(q2, pk2(sc0, sc1)));
    p0 = pf.x; p1 = pf.y;
}

// ---------------- scratch (no allocations allowed) ----------------
__device__ __nv_bfloat16 g_hh[TOK * DIM],  g_hl[TOK * DIM];
__device__ float g_qkv[TOK * 3 * DIM];
__device__ __nv_bfloat16 g_qh[NB * NH * S_LEN * HD];
__device__ __nv_bfloat16 g_kh[NB * NH * S_LEN * HD];
__device__ __nv_bfloat16 g_vh[NB * NH * S_LEN * HD];
__device__ __nv_bfloat16 g_atth[TOK * DIM], g_attl[TOK * DIM];
__device__ float g_x1[TOK * DIM];
__device__ __nv_bfloat16 g_midh[TOK * 4 * DIM], g_midl[TOK * 4 * DIM];
__device__ __nv_bfloat16 g_wqkvh[3 * DIM * DIM], g_wqkvl[3 * DIM * DIM];
__device__ __nv_bfloat16 g_wprojh[DIM * DIM],    g_wprojl[DIM * DIM];
__device__ __nv_bfloat16 g_wfc1h[4 * DIM * DIM], g_wfc1l[4 * DIM * DIM];
__device__ __nv_bfloat16 g_wfc2h[4 * DIM * DIM], g_wfc2l[4 * DIM * DIM];

__device__ __forceinline__ void split_bf16(float v, __nv_bfloat16& hi, __nv_bfloat16& lo)
{
    hi = __float2bfloat16(v);
    lo = __float2bfloat16(v - __bfloat162float(hi));
}

// ---------------- weight transpose + split ----------------
__global__ void __launch_bounds__(256) wsplit(const float* __restrict__ W,
                                              __nv_bfloat16* __restrict__ th,
                                              __nv_bfloat16* __restrict__ tl,
                                              int K, int N)
{
    __shared__ float t[32][33];
    int n0 = blockIdx.x * 32, k0 = blockIdx.y * 32;
    int j = threadIdx.x & 31, i0 = threadIdx.x >> 5;
#pragma unroll
    for (int it = 0; it < 4; it++) {
        int i = i0 + it * 8;
        t[i][j] = W[(size_t)(k0 + i) * N + n0 + j];
    }
    __syncthreads();
#pragma unroll
    for (int it = 0; it < 4; it++) {
        int i = i0 + it * 8;
        float v = t[j][i];
        __nv_bfloat16 hv, lv; split_bf16(v, hv, lv);
        size_t o = (size_t)(n0 + i) * K + k0 + j;
        th[o] = hv; tl[o] = lv;
    }
}

// ---------------- LayerNorm -> bf16 hi/lo ----------------
__global__ void __launch_bounds__(256) ln_kernel(const float* __restrict__ x,
                                                 const float* __restrict__ g,
                                                 const float* __restrict__ b,
                                                 __nv_bfloat16* __restrict__ oh,
                                                 __nv_bfloat16* __restrict__ ol)
{
    int row = blockIdx.x;
    int t = threadIdx.x;
    const float2* xr = (const float2*)(x + (size_t)row * DIM);
    float2 v = xr[t];
    float s = v.x + v.y;
    float ss = v.x * v.x + v.y * v.y;
#pragma unroll
    for (int m = 16; m; m >>= 1) {
        s  += __shfl_xor_sync(0xffffffffu, s, m);
        ss += __shfl_xor_sync(0xffffffffu, ss, m);
    }
    __shared__ float sh[16];
    int w = t >> 5;
    if ((t & 31) == 0) { sh[w] = s; sh[8 + w] = ss; }
    __syncthreads();
    s = 0.f; ss = 0.f;
#pragma unroll
    for (int i = 0; i < 8; i++) { s += sh[i]; ss += sh[8 + i]; }
    float mu  = s * (1.f / DIM);
    float var = ss * (1.f / DIM) - mu * mu;
    float inv = rsqrtf(var + 1e-5f);
    float2 gg = ((const float2*)g)[t];
    float2 bb = ((const float2*)b)[t];
    float vx = (v.x - mu) * inv * gg.x + bb.x;
    float vy = (v.y - mu) * inv * gg.y + bb.y;
    size_t idx = (size_t)row * DIM + 2 * t;
    __nv_bfloat16 h0, l0, h1, l1;
    split_bf16(vx, h0, l0); split_bf16(vy, h1, l1);
    oh[idx] = h0; oh[idx + 1] = h1;
    ol[idx] = l0; ol[idx + 1] = l1;
}

// ---------------- RoPE + bf16 convert ----------------
__global__ void __launch_bounds__(256) rope_bf16(const float* __restrict__ qkv,
                                                 const float* __restrict__ cb,
                                                 const float* __restrict__ sb,
                                                 __nv_bfloat16* __restrict__ qh,
                                                 __nv_bfloat16* __restrict__ kh,
                                                 __nv_bfloat16* __restrict__ vh)
{
    int t = blockIdx.x * blockDim.x + threadIdx.x;
    int d = t & 31, hh = (t >> 5) & 7, tok = t >> 8;
    int s = tok & (S_LEN - 1), b = tok >> 11;
    int bh = b * NH + hh;
    const float* row = qkv + (size_t)tok * (3 * DIM);
    float c0 = cb[s * HD + d], c1 = cb[s * HD + d + 32];
    float s0 = sb[s * HD + d], s1 = sb[s * HD + d + 32];
    float q0 = row[hh * HD + d],        q1 = row[hh * HD + d + 32];
    float k0 = row[DIM + hh * HD + d],  k1 = row[DIM + hh * HD + d + 32];
    float v0 = row[2 * DIM + hh * HD + d], v1 = row[2 * DIM + hh * HD + d + 32];
    float rq0 = (q0 * c0 - q1 * s0) * 0.125f;
    float rq1 = (q1 * c1 + q0 * s1) * 0.125f;
    float rk0 = k0 * c0 - k1 * s0;
    float rk1 = k1 * c1 + k0 * s1;
    size_t o = ((size_t)bh * S_LEN + s) * HD + d;
    qh[o] = __float2bfloat16(rq0); qh[o + 32] = __float2bfloat16(rq1);
    kh[o] = __float2bfloat16(rk0); kh[o + 32] = __float2bfloat16(rk1);
    vh[o] = __float2bfloat16(v0);  vh[o + 32] = __float2bfloat16(v1);
}

// ---------------- mma.sync bf16x3 GEMM, cp.async double-buffered ----------------
__device__ __forceinline__ float gelu_f(float x)
{
    return 0.5f * x * (1.f + erff(x * 0.7071067811865476f));
}

#define GPAD 40
#define GTILE (128 * GPAD)                 // bf16 per tile (5120)
#define GTILE_B (GTILE * 2)                // bytes per tile (10240)
#define GSTAGE_B (4 * GTILE_B)             // bytes per stage (40960)
#define GEMM_SMEM (2 * GSTAGE_B)           // 81920

template <int EPI, int OUT>
__global__ void __launch_bounds__(256) mma_gemm(const __nv_bfloat16* __restrict__ Ah,
                                                const __nv_bfloat16* __restrict__ Al,
                                                const __nv_bfloat16* __restrict__ Bh,
                                                const __nv_bfloat16* __restrict__ Bl,
                                                const float* __restrict__ bias,
                                                const float* __restrict__ R,
                                                float* __restrict__ C,
                                                __nv_bfloat16* __restrict__ Ch,
                                                __nv_bfloat16* __restrict__ Cl,
                                                int M, int N, int K)
{
    extern __shared__ __align__(16) char dsm[];
    uint32_t uBase = smem_u32(dsm);

    int tid = threadIdx.x, lane = tid & 31, wid = tid >> 5;
    int wm = wid & 3, wn = wid >> 2;
    int m0 = blockIdx.y * 128, n0 = blockIdx.x * 128;

    uint32_t aoff = (uint32_t)((lane & 15) * GPAD + (lane >> 4) * 8) * 2;
    uint32_t boff = (uint32_t)((((lane >> 4) & 1) * 8 + (lane & 7)) * GPAD +
                               ((lane >> 3) & 1) * 8) * 2;

    // per-thread load coords (2 chunks of 16B per tile)
    int r0 = tid >> 2, sg0 = tid & 3;
    int r1 = (tid + 256) >> 2, sg1 = (tid + 256) & 3;
    uint32_t d0 = (uint32_t)(r0 * GPAD + sg0 * 8) * 2;
    uint32_t d1 = (uint32_t)(r1 * GPAD + sg1 * 8) * 2;

    float acc[2][8][4];
#pragma unroll
    for (int i = 0; i < 2; i++)
#pragma unroll
        for (int j = 0; j < 8; j++)
#pragma unroll
            for (int c = 0; c < 4; c++) acc[i][j][c] = 0.f;

    int nT = K >> 5;

    // prologue: stage 0
    {
        uint32_t sb = uBase;
        cpa16(sb + d0,                &Ah[(size_t)(m0 + r0) * K + sg0 * 8]);
        cpa16(sb + d1,                &Ah[(size_t)(m0 + r1) * K + sg1 * 8]);
        cpa16(sb + GTILE_B + d0,      &Al[(size_t)(m0 + r0) * K + sg0 * 8]);
        cpa16(sb + GTILE_B + d1,      &Al[(size_t)(m0 + r1) * K + sg1 * 8]);
        cpa16(sb + 2 * GTILE_B + d0,  &Bh[(size_t)(n0 + r0) * K + sg0 * 8]);
        cpa16(sb + 2 * GTILE_B + d1,  &Bh[(size_t)(n0 + r1) * K + sg1 * 8]);
        cpa16(sb + 3 * GTILE_B + d0,  &Bl[(size_t)(n0 + r0) * K + sg0 * 8]);
        cpa16(sb + 3 * GTILE_B + d1,  &Bl[(size_t)(n0 + r1) * K + sg1 * 8]);
        CP_COMMIT();
    }

    for (int t = 0; t < nT; ++t) {
        CP_WAIT0();
        __syncthreads();
        if (t + 1 < nT) {
            int kk = (t + 1) * 32;
            uint32_t sb = uBase + ((t + 1) & 1) * GSTAGE_B;
            cpa16(sb + d0,                &Ah[(size_t)(m0 + r0) * K + kk + sg0 * 8]);
            cpa16(sb + d1,                &Ah[(size_t)(m0 + r1) * K + kk + sg1 * 8]);
            cpa16(sb + GTILE_B + d0,      &Al[(size_t)(m0 + r0) * K + kk + sg0 * 8]);
            cpa16(sb + GTILE_B + d1,      &Al[(size_t)(m0 + r1) * K + kk + sg1 * 8]);
            cpa16(sb + 2 * GTILE_B + d0,  &Bh[(size_t)(n0 + r0) * K + kk + sg0 * 8]);
            cpa16(sb + 2 * GTILE_B + d1,  &Bh[(size_t)(n0 + r1) * K + kk + sg1 * 8]);
            cpa16(sb + 3 * GTILE_B + d0,  &Bl[(size_t)(n0 + r0) * K + kk + sg0 * 8]);
            cpa16(sb + 3 * GTILE_B + d1,  &Bl[(size_t)(n0 + r1) * K + kk + sg1 * 8]);
            CP_COMMIT();
        }
        uint32_t uAh = uBase + (t & 1) * GSTAGE_B;
        uint32_t uAl = uAh + GTILE_B;
        uint32_t uBh = uAh + 2 * GTILE_B;
        uint32_t uBl = uAh + 3 * GTILE_B;

#pragma unroll
        for (int k16 = 0; k16 < 2; ++k16) {
            uint32_t kb = (uint32_t)(k16 * 16 * 2);
            uint32_t ah[2][4], al[2][4];
#pragma unroll
            for (int mt = 0; mt < 2; ++mt) {
                uint32_t ro = (uint32_t)((wm * 32 + mt * 16) * GPAD * 2) + kb + aoff;
                ldsm_x4(ah[mt], uAh + ro);
                ldsm_x4(al[mt], uAl + ro);
            }
            uint32_t bh[4][4], bl[4][4];
#pragma unroll
            for (int p = 0; p < 4; ++p) {
                uint32_t ro = (uint32_t)((wn * 64 + p * 16) * GPAD * 2) + kb + boff;
                ldsm_x4(bh[p], uBh + ro);
                ldsm_x4(bl[p], uBl + ro);
            }
#pragma unroll
            for (int mt = 0; mt < 2; ++mt)
#pragma unroll
                for (int nt = 0; nt < 8; ++nt) {
                    const uint32_t* fh = &bh[nt >> 1][(nt & 1) * 2];
                    const uint32_t* fl = &bl[nt >> 1][(nt & 1) * 2];
                    mma16816(acc[mt][nt], ah[mt], fh);
                    mma16816(acc[mt][nt], ah[mt], fl);
                    mma16816(acc[mt][nt], al[mt], fh);
                }
        }
    }

#pragma unroll
    for (int mt = 0; mt < 2; ++mt) {
#pragma unroll
        for (int nt = 0; nt < 8; ++nt) {
            int row = m0 + wm * 32 + mt * 16 + (lane >> 2);
            int col = n0 + wn * 64 + nt * 8 + (lane & 3) * 2;
            float b0 = bias[col], b1 = bias[col + 1];
#pragma unroll
            for (int half = 0; half < 2; ++half) {
                int r = row + half * 8;
                float v0 = acc[mt][nt][half * 2 + 0] + b0;
                float v1 = acc[mt][nt][half * 2 + 1] + b1;
                if (EPI == 1) { v0 = gelu_f(v0); v1 = gelu_f(v1); }
                size_t off = (size_t)r * N + col;
                if (EPI == 2) {
                    float2 rr = *(const float2*)&R[off];
                    v0 += rr.x; v1 += rr.y;
                }
                if (OUT == 0) {
                    *(float2*)&C[off] = make_float2(v0, v1);
                } else {
                    __nv_bfloat16 h0, l0, h1, l1;
                    split_bf16(v0, h0, l0); split_bf16(v1, h1, l1);
                    *(__nv_bfloat162*)&Ch[off] = __nv_bfloat162(h0, h1);
                    *(__nv_bfloat162*)&Cl[off] = __nv_bfloat162(l0, l1);
                }
            }
        }
    }
}

// ---------------- tensor-core flash attention, cp.async double-buffered K/V ----------------
#define APITCH 72
#define AQ_B   (128 * APITCH * 2)          // 18432
#define AKV_B  (64 * APITCH * 2)           // 9216
#define ASTAGE_B (2 * AKV_B)               // K+V per stage
#define ATT_SMEM (AQ_B + 2 * ASTAGE_B)     // 55296

__global__ void __launch_bounds__(256) attn_kernel(const __nv_bfloat16* __restrict__ qh,
                                                   const __nv_bfloat16* __restrict__ kh,
                                                   const __nv_bfloat16* __restrict__ vh,
                                                   __nv_bfloat16* __restrict__ oh,
                                                   __nv_bfloat16* __restrict__ ol)
{
    extern __shared__ __align__(16) char dsm[];
    __nv_bfloat16* Qs = (__nv_bfloat16*)dsm;
    uint32_t uQ = smem_u32(dsm);

    int tid = threadIdx.x, lane = tid & 31, w = tid >> 5;
    int qt = blockIdx.x, h = blockIdx.y, b = blockIdx.z;
    int bh = b * NH + h;

    const __nv_bfloat16* Qg = qh + ((size_t)bh * S_LEN + qt * 128) * HD;
    const __nv_bfloat16* Kg = kh + (size_t)bh * S_LEN * HD;
    const __nv_bfloat16* Vg = vh + (size_t)bh * S_LEN * HD;

    // per-thread K/V load coords (2 chunks of 16B each for K and V)
    int r0 = tid >> 3, sg0 = tid & 7;
    int r1 = (tid + 256) >> 3, sg1 = (tid + 256) & 7;
    uint32_t kd0 = (uint32_t)(r0 * APITCH + sg0 * 8) * 2;
    uint32_t kd1 = (uint32_t)(r1 * APITCH + sg1 * 8) * 2;

    // prologue: issue K/V stage 0, then stage Q
    {
        uint32_t sb = uQ + AQ_B;
        cpa16(sb + kd0,         &Kg[r0 * HD + sg0 * 8]);
        cpa16(sb + kd1,         &Kg[r1 * HD + sg1 * 8]);
        cpa16(sb + AKV_B + kd0, &Vg[r0 * HD + sg0 * 8]);
        cpa16(sb + AKV_B + kd1, &Vg[r1 * HD + sg1 * 8]);
        CP_COMMIT();
    }
#pragma unroll
    for (int it = 0; it < 4; ++it) {
        int u = tid + it * 256;
        int r = u >> 3, sg = u & 7;
        *(uint4*)&Qs[r * APITCH + sg * 8] = *(const uint4*)&Qg[r * HD + sg * 8];
    }
    __syncthreads();

    // Q fragments
    uint32_t aq[4][4];
    {
        uint32_t row = (uint32_t)(w * 16 + (lane & 15));
        uint32_t segb = (uint32_t)((lane >> 4) << 3);
#pragma unroll
        for (int kc = 0; kc < 4; ++kc)
            ldsm_x4(aq[kc], uQ + 2u * (row * APITCH + kc * 16 + segb));
    }

    uint32_t kboff = 2u * ((((lane >> 4) & 1) * 8 + (lane & 7)) * APITCH + ((lane >> 3) & 1) * 8);
    uint32_t vboff = 2u * ((((lane >> 3) & 1) * 8 + (lane & 7)) * APITCH + ((lane >> 4) & 1) * 8);

    float o[8][4];
#pragma unroll
    for (int a = 0; a < 8; a++)
#pragma unroll
        for (int c = 0; c < 4; c++) o[a][c] = 0.f;
    float mA = -1e30f, mB = -1e30f, lA = 0.f, lB = 0.f;
    const float L2E = 1.4426950408889634f;

    const int NT = S_LEN / 64;
    for (int nt = 0; nt < NT; ++nt) {
        CP_WAIT0();
        __syncthreads();
        if (nt + 1 < NT) {
            uint32_t sb = uQ + AQ_B + ((nt + 1) & 1) * ASTAGE_B;
            int base = (nt + 1) * 64;
            cpa16(sb + kd0,         &Kg[(base + r0) * HD + sg0 * 8]);
            cpa16(sb + kd1,         &Kg[(base + r1) * HD + sg1 * 8]);
            cpa16(sb + AKV_B + kd0, &Vg[(base + r0) * HD + sg0 * 8]);
            cpa16(sb + AKV_B + kd1, &Vg[(base + r1) * HD + sg1 * 8]);
            CP_COMMIT();
        }
        uint32_t uK = uQ + AQ_B + (nt & 1) * ASTAGE_B;
        uint32_t uV = uK + AKV_B;

        // S = Q K^T
        float sf[8][4];
#pragma unroll
        for (int a = 0; a < 8; a++)
#pragma unroll
            for (int c = 0; c < 4; c++) sf[a][c] = 0.f;
#pragma unroll
        for (int kc = 0; kc < 4; ++kc) {
            uint32_t bk[4][4];
#pragma unroll
            for (int np = 0; np < 4; ++np)
                ldsm_x4(bk[np], uK + kboff + 2u * (np * 16 * APITCH + kc * 16));
#pragma unroll
            for (int np = 0; np < 4; ++np) {
                mma16816(sf[2 * np],     aq[kc], &bk[np][0]);
                mma16816(sf[2 * np + 1], aq[kc], &bk[np][2]);
            }
        }

        // online softmax
        float txA = -1e30f, txB = -1e30f;
#pragma unroll
        for (int a = 0; a < 8; a++) {
            txA = fmaxf(txA, fmaxf(sf[a][0], sf[a][1]));
            txB = fmaxf(txB, fmaxf(sf[a][2], sf[a][3]));
        }
        txA = fmaxf(txA, __shfl_xor_sync(0xffffffffu, txA, 1));
        txA = fmaxf(txA, __shfl_xor_sync(0xffffffffu, txA, 2));
        txB = fmaxf(txB, __shfl_xor_sync(0xffffffffu, txB, 1));
        txB = fmaxf(txB, __shfl_xor_sync(0xffffffffu, txB, 2));
        float mnA = fmaxf(mA, txA), mnB = fmaxf(mB, txB);
        float aAl = __expf(mA - mnA), aBl = __expf(mB - mnB);
        mA = mnA; mB = mnB;
        ull nmA2 = pkdup(-mnA * L2E), nmB2 = pkdup(-mnB * L2E);
        float sA = 0.f, sB = 0.f;
#pragma unroll
        for (int a = 0; a < 8; a++) {
            if (a & 1) {
                sf[a][0] = __expf(sf[a][0] - mnA);
                sf[a][1] = __expf(sf[a][1] - mnA);
                sf[a][2] = __expf(sf[a][2] - mnB);
                sf[a][3] = __expf(sf[a][3] - mnB);
            } else {
                exp2pk(pk2(sf[a][0], sf[a][1]), nmA2, sf[a][0], sf[a][1]);
                exp2pk(pk2(sf[a][2], sf[a][3]), nmB2, sf[a][2], sf[a][3]);
            }
            sA += sf[a][0] + sf[a][1];
            sB += sf[a][2] + sf[a][3];
        }
        sA += __shfl_xor_sync(0xffffffffu, sA, 1);
        sA += __shfl_xor_sync(0xffffffffu, sA, 2);
        sB += __shfl_xor_sync(0xffffffffu, sB, 1);
        sB += __shfl_xor_sync(0xffffffffu, sB, 2);
        lA = lA * aAl + sA;
        lB = lB * aBl + sB;
#pragma unroll
        for (int a = 0; a < 8; a++) {
            o[a][0] *= aAl; o[a][1] *= aAl;
            o[a][2] *= aBl; o[a][3] *= aBl;
        }

        // O += P V
#pragma unroll
        for (int kc = 0; kc < 4; ++kc) {
            uint32_t bv[4][4];
#pragma unroll
            for (int np = 0; np < 4; ++np)
                ldsm_x4t(bv[np], uV + vboff + 2u * (kc * 16 * APITCH + np * 16));
            uint32_t pa[4];
            pa[0] = cvt_bf16x2(sf[2 * kc][1],     sf[2 * kc][0]);
            pa[1] = cvt_bf16x2(sf[2 * kc][3],     sf[2 * kc][2]);
            pa[2] = cvt_bf16x2(sf[2 * kc + 1][1], sf[2 * kc + 1][0]);
            pa[3] = cvt_bf16x2(sf[2 * kc + 1][3], sf[2 * kc + 1][2]);
#pragma unroll
            for (int np = 0; np < 4; ++np) {
                mma16816(o[2 * np],     pa, &bv[np][0]);
                mma16816(o[2 * np + 1], pa, &bv[np][2]);
            }
        }
    }

    // epilogue
    float iA = 1.f / lA, iB = 1.f / lB;
    int rA = b * S_LEN + qt * 128 + w * 16 + (lane >> 2);
    int rB = rA + 8;
    int cb0 = h * HD + (lane & 3) * 2;
#pragma unroll
    for (int a = 0; a < 8; a++) {
        int col = cb0 + a * 8;
        float v0 = o[a][0] * iA, v1 = o[a][1] * iA;
        float v2 = o[a][2] * iB, v3 = o[a][3] * iB;
        __nv_bfloat16 h0, l0, h1, l1, h2, l2, h3, l3;
        split_bf16(v0, h0, l0); split_bf16(v1, h1, l1);
        split_bf16(v2, h2, l2); split_bf16(v3, h3, l3);
        *(__nv_bfloat162*)&oh[(size_t)rA * DIM + col] = __nv_bfloat162(h0, h1);
        *(__nv_bfloat162*)&ol[(size_t)rA * DIM + col] = __nv_bfloat162(l0, l1);
        *(__nv_bfloat162*)&oh[(size_t)rB * DIM + col] = __nv_bfloat162(h2, h3);
        *(__nv_bfloat162*)&ol[(size_t)rB * DIM + col] = __nv_bfloat162(l2, l3);
    }
}

// ---------------- launcher ----------------
extern "C" void kernel_launch(void* const* d_in, const int* in_sizes, int n_in,
                              void* d_out, int out_size)
{
    const float* x        = (const float*)d_in[0];
    const float* rope_cos = (const float*)d_in[1];
    const float* rope_sin = (const float*)d_in[2];
    const float* n1g      = (const float*)d_in[3];
    const float* n1b      = (const float*)d_in[4];
    const float* n2g      = (const float*)d_in[5];
    const float* n2b      = (const float*)d_in[6];
    const float* w_qkv    = (const float*)d_in[7];
    const float* b_qkv    = (const float*)d_in[8];
    const float* w_proj   = (const float*)d_in[9];
    const float* b_proj   = (const float*)d_in[10];
    const float* w_fc1    = (const float*)d_in[11];
    const float* b_fc1    = (const float*)d_in[12];
    const float* w_fc2    = (const float*)d_in[13];
    const float* b_fc2    = (const float*)d_in[14];
    float* out = (float*)d_out;

    __nv_bfloat16 *phh, *phl, *patth, *pattl, *pmidh, *pmidl;
    __nv_bfloat16 *pqh, *pkh, *pvh;
    __nv_bfloat16 *wqh, *wql, *wph, *wpl, *w1h, *w1l, *w2h, *w2l;
    float *pqkv, *px1;
    cudaGetSymbolAddress((void**)&phh,   g_hh);
    cudaGetSymbolAddress((void**)&phl,   g_hl);
    cudaGetSymbolAddress((void**)&pqkv,  g_qkv);
    cudaGetSymbolAddress((void**)&pqh,   g_qh);
    cudaGetSymbolAddress((void**)&pkh,   g_kh);
    cudaGetSymbolAddress((void**)&pvh,   g_vh);
    cudaGetSymbolAddress((void**)&patth, g_atth);
    cudaGetSymbolAddress((void**)&pattl, g_attl);
    cudaGetSymbolAddress((void**)&px1,   g_x1);
    cudaGetSymbolAddress((void**)&pmidh, g_midh);
    cudaGetSymbolAddress((void**)&pmidl, g_midl);
    cudaGetSymbolAddress((void**)&wqh, g_wqkvh);
    cudaGetSymbolAddress((void**)&wql, g_wqkvl);
    cudaGetSymbolAddress((void**)&wph, g_wprojh);
    cudaGetSymbolAddress((void**)&wpl, g_wprojl);
    cudaGetSymbolAddress((void**)&w1h, g_wfc1h);
    cudaGetSymbolAddress((void**)&w1l, g_wfc1l);
    cudaGetSymbolAddress((void**)&w2h, g_wfc2h);
    cudaGetSymbolAddress((void**)&w2l, g_wfc2l);

    cudaFuncSetAttribute(mma_gemm<0,0>, cudaFuncAttributeMaxDynamicSharedMemorySize, GEMM_SMEM);
    cudaFuncSetAttribute(mma_gemm<2,0>, cudaFuncAttributeMaxDynamicSharedMemorySize, GEMM_SMEM);
    cudaFuncSetAttribute(mma_gemm<1,1>, cudaFuncAttributeMaxDynamicSharedMemorySize, GEMM_SMEM);
    cudaFuncSetAttribute(attn_kernel, cudaFuncAttributeMaxDynamicSharedMemorySize, ATT_SMEM);

    // 0) weight transpose + bf16 split
    wsplit<<<dim3(3 * DIM / 32, DIM / 32), 256>>>(w_qkv,  wqh, wql, DIM,     3 * DIM);
    wsplit<<<dim3(DIM / 32,     DIM / 32), 256>>>(w_proj, wph, wpl, DIM,     DIM);
    wsplit<<<dim3(4 * DIM / 32, DIM / 32), 256>>>(w_fc1,  w1h, w1l, DIM,     4 * DIM);
    wsplit<<<dim3(DIM / 32, 4 * DIM / 32), 256>>>(w_fc2,  w2h, w2l, 4 * DIM, DIM);

    // 1) LN1
    ln_kernel<<<TOK, 256>>>(x, n1g, n1b, phh, phl);
    // 2) QKV GEMM
    mma_gemm<0,0><<<dim3(3 * DIM / 128, TOK / 128), 256, GEMM_SMEM>>>(
        phh, phl, wqh, wql, b_qkv, nullptr, pqkv, nullptr, nullptr, TOK, 3 * DIM, DIM);
    // 3) RoPE + bf16 convert
    rope_bf16<<<(TOK * NH * 32) / 256, 256>>>(pqkv, rope_cos, rope_sin, pqh, pkh, pvh);
    // 4) attention
    attn_kernel<<<dim3(S_LEN / 128, NH, NB), 256, ATT_SMEM>>>(pqh, pkh, pvh, patth, pattl);
    // 5) proj + bias + residual(x)
    mma_gemm<2,0><<<dim3(DIM / 128, TOK / 128), 256, GEMM_SMEM>>>(
        patth, pattl, wph, wpl, b_proj, x, px1, nullptr, nullptr, TOK, DIM, DIM);
    // 6) LN2
    ln_kernel<<<TOK, 256>>>(px1, n2g, n2b, phh, phl);
    // 7) FC1 + bias + GELU
    mma_gemm<1,1><<<dim3(4 * DIM / 128, TOK / 128), 256, GEMM_SMEM>>>(
        phh, phl, w1h, w1l, b_fc1, nullptr, nullptr, pmidh, pmidl, TOK, 4 * DIM, DIM);
    // 8) FC2 + bias + residual(x1) -> out
    mma_gemm<2,0><<<dim3(DIM / 128, TOK / 128), 256, GEMM_SMEM>>>(
        pmidh, pmidl, w2h, w2l, b_fc2, px1, out, nullptr, nullptr, TOK, DIM, 4 * DIM);
}